// round 9
// baseline (speedup 1.0000x reference)
#include <cuda_runtime.h>
#include <cuda_fp16.h>
#include <stdint.h>
#include <math.h>

#define BATCH 32
#define SEQ   2048
#define DIM   1024
#define UNITS 1024

// ---------------------------------------------------------------------------
// Scratch (no device allocs allowed)
// ---------------------------------------------------------------------------
#define NSPLIT 16
__device__ __half g_values_h[BATCH * SEQ * DIM];   // fp16 copy of values (128MB)
__device__ __half g_W1T_h[UNITS * DIM];            // W1 transposed, fp16 [u][d]
__device__ float  g_qb[BATCH * UNITS];             // query@W2 + b2 + b1
__device__ float  g_scores[BATCH * SEQ];
__device__ float  g_weights[BATCH * SEQ];
__device__ float  g_ctx_part[NSPLIT][BATCH * DIM];

// ---------------------------------------------------------------------------
// PTX helpers
// ---------------------------------------------------------------------------
__device__ __forceinline__ uint32_t smem_u32(const void* p) {
    uint32_t a;
    asm("{ .reg .u64 t; cvta.to.shared.u64 t, %1; cvt.u32.u64 %0, t; }" : "=r"(a) : "l"(p));
    return a;
}
#define CP_ASYNC16(s, g) \
    asm volatile("cp.async.cg.shared.global [%0], [%1], 16;" :: "r"(s), "l"(g))
#define CP_COMMIT() asm volatile("cp.async.commit_group;" ::: "memory")
#define CP_WAIT1()  asm volatile("cp.async.wait_group 1;" ::: "memory")

// mma.sync m16n8k16 fp16 inputs, fp32 accum (baseline PTX, sm_80+)
__device__ __forceinline__ void mma_f16(float* d, const uint32_t* a, const uint32_t* b) {
    asm volatile(
        "mma.sync.aligned.m16n8k16.row.col.f32.f16.f16.f32 "
        "{%0,%1,%2,%3}, {%4,%5,%6,%7}, {%8,%9}, {%0,%1,%2,%3};"
        : "+f"(d[0]), "+f"(d[1]), "+f"(d[2]), "+f"(d[3])
        : "r"(a[0]), "r"(a[1]), "r"(a[2]), "r"(a[3]), "r"(b[0]), "r"(b[1]));
}

// ldmatrix x4 (baseline PTX, sm_75+)
__device__ __forceinline__ void ldsm_x4(uint32_t* r, uint32_t saddr) {
    asm volatile("ldmatrix.sync.aligned.m8n8.x4.shared.b16 {%0,%1,%2,%3}, [%4];"
        : "=r"(r[0]), "=r"(r[1]), "=r"(r[2]), "=r"(r[3]) : "r"(saddr));
}

// ---------------------------------------------------------------------------
// FMA-only tanh (no MUFU): abs err < ~5e-5
// ---------------------------------------------------------------------------
__device__ __forceinline__ float tanh_fast(float x) {
    float ax = fminf(fabsf(x), 10.0f);
    float t  = ax * 2.885390081777927f;
    float fn = t + 12582912.0f;
    int   n  = __float_as_int(fn) - __float_as_int(12582912.0f);
    float f  = t - (fn - 12582912.0f);
    float p  = 9.6181e-3f;
    p = fmaf(p, f, 5.5504e-2f);
    p = fmaf(p, f, 2.4022651e-1f);
    p = fmaf(p, f, 6.9314718e-1f);
    p = fmaf(p, f, 1.0f);
    float e = __int_as_float(__float_as_int(p) + (n << 23));
    float d = e + 1.0f;
    float r = __int_as_float(0x7EF311C3u - __float_as_int(d));
    r = r * fmaf(-d, r, 2.0f);
    r = r * fmaf(-d, r, 2.0f);
    float th = fmaf(-2.0f, r, 1.0f);
    return __int_as_float(__float_as_int(th) | (__float_as_int(x) & 0x80000000));
}

// ---------------------------------------------------------------------------
// Prep A: values fp32 -> fp16 (8 elems/thread)
// ---------------------------------------------------------------------------
__global__ __launch_bounds__(256) void convert_values_kernel(const float4* __restrict__ in)
{
    const size_t idx = (size_t)blockIdx.x * 256 + threadIdx.x;
    float4 v0 = in[idx * 2];
    float4 v1 = in[idx * 2 + 1];
    __half2 h0 = __floats2half2_rn(v0.x, v0.y);
    __half2 h1 = __floats2half2_rn(v0.z, v0.w);
    __half2 h2 = __floats2half2_rn(v1.x, v1.y);
    __half2 h3 = __floats2half2_rn(v1.z, v1.w);
    uint4 o;
    o.x = *(uint32_t*)&h0; o.y = *(uint32_t*)&h1;
    o.z = *(uint32_t*)&h2; o.w = *(uint32_t*)&h3;
    ((uint4*)g_values_h)[idx] = o;
}

// ---------------------------------------------------------------------------
// Prep B: W1 [d][u] fp32 -> g_W1T_h [u][d] fp16
// ---------------------------------------------------------------------------
__global__ __launch_bounds__(256) void transpose_w1_kernel(const float* __restrict__ W1)
{
    __shared__ float t[32][33];
    const int d0 = blockIdx.x * 32;
    const int u0 = blockIdx.y * 32;
    const int tx = threadIdx.x & 31;
    const int ty = threadIdx.x >> 5;
    #pragma unroll
    for (int i = 0; i < 4; i++) {
        int r = ty + i * 8;
        t[r][tx] = W1[(size_t)(d0 + r) * UNITS + u0 + tx];
    }
    __syncthreads();
    #pragma unroll
    for (int i = 0; i < 4; i++) {
        int r = ty + i * 8;
        g_W1T_h[(size_t)(u0 + r) * DIM + d0 + tx] = __float2half_rn(t[tx][r]);
    }
}

// ---------------------------------------------------------------------------
// Kernel 1: g_qb[b][u] = query[b,:] @ W2[:,u] + b2[u] + b1[u]  (fp32)
// ---------------------------------------------------------------------------
__global__ __launch_bounds__(256) void qproj_kernel(
    const float* __restrict__ query, const float* __restrict__ W2,
    const float* __restrict__ b1, const float* __restrict__ b2)
{
    __shared__ float qrow[DIM];
    const int b = blockIdx.x;
    for (int i = threadIdx.x; i < DIM; i += blockDim.x)
        qrow[i] = query[b * DIM + i];
    __syncthreads();
    for (int u = threadIdx.x; u < UNITS; u += blockDim.x) {
        float acc = 0.f;
        #pragma unroll 8
        for (int d = 0; d < DIM; d++)
            acc = fmaf(qrow[d], W2[d * UNITS + u], acc);
        g_qb[b * UNITS + u] = acc + b1[u] + b2[u];
    }
}

// ---------------------------------------------------------------------------
// Kernel 2: fused score GEMM via mma.sync fp16 (m16n8k16) + ldmatrix
// CTA tile 128(M) x 256(N), 4 N-passes, K chunks of 64 -> 64 flat chunks.
// 512 threads = 16 warps (4M x 4N), warp tile 32x64 (mi=2, ni=8).
// 3-stage cp.async pipeline, one __syncthreads per chunk.
// ---------------------------------------------------------------------------
#define KC        64                   // K per chunk
#define A_PITCH_H 72
#define B_PITCH_H 72
#define A_STAGE_H (128 * A_PITCH_H)    // 9216 halfs
#define B_STAGE_H (256 * B_PITCH_H)    // 18432 halfs
#define OFF_B_H   (3 * A_STAGE_H)      // 27648 halfs
#define SMEM_HALFS (OFF_B_H + 3 * B_STAGE_H)         // 82944 halfs
#define OFF_SC_BYTES (SMEM_HALFS * 2)                // 165888
#define SMEM_SCORE_BYTES (OFF_SC_BYTES + 128 * 4)    // 166400

__device__ __forceinline__ void load_chunk(uint32_t sb, int stage, int m0, int c, int tid)
{
    const int n0 = (c >> 4) * 256;
    const int k0 = (c & 15) * KC;
    const uint32_t a_s = sb + stage * A_STAGE_H * 2;
    const uint32_t b_s = sb + (OFF_B_H + stage * B_STAGE_H) * 2;
    // A: values_h tile 128 x 64 halfs (1024 16B chunks / 512 thr = 2)
    #pragma unroll
    for (int t = 0; t < 2; t++) {
        int idx = tid + t * 512;
        int r = idx >> 3, cc = idx & 7;
        CP_ASYNC16(a_s + r * 144 + cc * 16,
                   g_values_h + (size_t)(m0 + r) * DIM + k0 + cc * 8);
    }
    // B: W1T_h tile 256 x 64 halfs (2048 chunks / 512 thr = 4)
    #pragma unroll
    for (int t = 0; t < 4; t++) {
        int idx = tid + t * 512;
        int r = idx >> 3, cc = idx & 7;
        CP_ASYNC16(b_s + r * 144 + cc * 16,
                   g_W1T_h + (size_t)(n0 + r) * DIM + k0 + cc * 8);
    }
}

__global__ __launch_bounds__(512, 1) void score_kernel(const float* __restrict__ V)
{
    extern __shared__ __align__(16) char smraw[];
    float* s_sc = (float*)(smraw + OFF_SC_BYTES);
    const uint32_t sb = smem_u32(smraw);

    const int tid  = threadIdx.x;
    const int warp = tid >> 5;
    const int lane = tid & 31;
    const int wm   = warp >> 2;          // 0..3 (M)
    const int wn   = warp & 3;           // 0..3 (N)
    const int grp  = lane >> 2;          // 0..7
    const int ctg  = lane & 3;           // 0..3
    const int m0   = blockIdx.x * 128;
    const int b    = m0 >> 11;

    // ldmatrix lane-addressing: row-in-16 and k-octet select
    const int lrow = ((lane >> 3) & 1) * 8 + (lane & 7);   // 0..15
    const int lkoc = ((lane >> 4) & 1) * 8;                // 0 or 8

    if (tid < 128) s_sc[tid] = 0.f;

    float p[2][2];
    p[0][0] = p[0][1] = p[1][0] = p[1][1] = 0.f;

    float acc[2][8][4];

    load_chunk(sb, 0, m0, 0, tid); CP_COMMIT();
    load_chunk(sb, 1, m0, 1, tid); CP_COMMIT();

    for (int c = 0; c < 64; c++) {
        const int stage = c % 3;
        CP_WAIT1();
        __syncthreads();
        if (c + 2 < 64)
            load_chunk(sb, (c + 2) % 3, m0, c + 2, tid);
        CP_COMMIT();

        if ((c & 15) == 0) {
            #pragma unroll
            for (int mi = 0; mi < 2; mi++)
                #pragma unroll
                for (int ni = 0; ni < 8; ni++)
                    #pragma unroll
                    for (int r = 0; r < 4; r++)
                        acc[mi][ni][r] = 0.f;
        }

        // base smem byte addresses for this stage's A / B tiles
        const uint32_t a_base = sb + stage * A_STAGE_H * 2
                              + ((wm * 32 + lrow) * A_PITCH_H + lkoc) * 2;
        const uint32_t b_base = sb + (OFF_B_H + stage * B_STAGE_H) * 2
                              + ((wn * 64 + lrow) * B_PITCH_H + lkoc) * 2;

        #pragma unroll
        for (int k16 = 0; k16 < KC / 16; k16++) {
            const int kb = k16 * 16;
            uint32_t afr[2][4], bfr[8][2];
            // A: one ldmatrix.x4 per 16-row mi tile -> afr[mi][0..3]
            #pragma unroll
            for (int mi = 0; mi < 2; mi++)
                ldsm_x4(afr[mi], a_base + (mi * 16 * A_PITCH_H + kb) * 2);
            // B: one ldmatrix.x4 per ni pair -> bfr[2p..2p+1][0..1]
            #pragma unroll
            for (int pr = 0; pr < 4; pr++) {
                uint32_t tmp[4];
                ldsm_x4(tmp, b_base + (pr * 16 * B_PITCH_H + kb) * 2);
                bfr[2 * pr][0]     = tmp[0];
                bfr[2 * pr + 1][0] = tmp[1];
                bfr[2 * pr][1]     = tmp[2];
                bfr[2 * pr + 1][1] = tmp[3];
            }
            #pragma unroll
            for (int mi = 0; mi < 2; mi++)
                #pragma unroll
                for (int ni = 0; ni < 8; ni++)
                    mma_f16(acc[mi][ni], afr[mi], bfr[ni]);
        }

        if ((c & 15) == 15) {
            // epilogue for this n-pass: tanh(acc + qb) * V (regs + gmem only)
            const int n0 = (c >> 4) * 256;
            #pragma unroll
            for (int ni = 0; ni < 8; ni++) {
                const int nloc = n0 + wn * 64 + ni * 8 + ctg * 2;
                const float2 q2 = *(const float2*)&g_qb[b * UNITS + nloc];
                const float2 v2 = *(const float2*)&V[nloc];
                #pragma unroll
                for (int mi = 0; mi < 2; mi++) {
                    p[mi][0] = fmaf(tanh_fast(acc[mi][ni][0] + q2.x), v2.x, p[mi][0]);
                    p[mi][0] = fmaf(tanh_fast(acc[mi][ni][1] + q2.y), v2.y, p[mi][0]);
                    p[mi][1] = fmaf(tanh_fast(acc[mi][ni][2] + q2.x), v2.x, p[mi][1]);
                    p[mi][1] = fmaf(tanh_fast(acc[mi][ni][3] + q2.y), v2.y, p[mi][1]);
                }
            }
        }
    }

    // reduce over quad lanes (ctg), then across the 4 n-warps via smem atomics
    #pragma unroll
    for (int mi = 0; mi < 2; mi++) {
        #pragma unroll
        for (int r = 0; r < 2; r++) {
            float v = p[mi][r];
            v += __shfl_xor_sync(0xffffffffu, v, 1);
            v += __shfl_xor_sync(0xffffffffu, v, 2);
            if (ctg == 0)
                atomicAdd(&s_sc[wm * 32 + mi * 16 + r * 8 + grp], v);
        }
    }
    __syncthreads();
    if (tid < 128) g_scores[m0 + tid] = s_sc[tid];
}

// ---------------------------------------------------------------------------
// Kernel 3: softmax over sequence axis
// ---------------------------------------------------------------------------
__global__ __launch_bounds__(256) void softmax_kernel(float* __restrict__ w_out)
{
    const int b   = blockIdx.x;
    const int tid = threadIdx.x;
    const float* sc = g_scores + b * SEQ;
    __shared__ float sred[8];

    float m = -1e30f;
    for (int i = tid; i < SEQ; i += 256) m = fmaxf(m, sc[i]);
    #pragma unroll
    for (int off = 16; off > 0; off >>= 1)
        m = fmaxf(m, __shfl_xor_sync(0xffffffffu, m, off));
    if ((tid & 31) == 0) sred[tid >> 5] = m;
    __syncthreads();
    if (tid == 0) {
        float mm = sred[0];
        #pragma unroll
        for (int i = 1; i < 8; i++) mm = fmaxf(mm, sred[i]);
        sred[0] = mm;
    }
    __syncthreads();
    const float bm = sred[0];
    __syncthreads();

    float sum = 0.f;
    for (int i = tid; i < SEQ; i += 256) {
        float e = __expf(sc[i] - bm);
        g_weights[b * SEQ + i] = e;
        sum += e;
    }
    #pragma unroll
    for (int off = 16; off > 0; off >>= 1)
        sum += __shfl_xor_sync(0xffffffffu, sum, off);
    if ((tid & 31) == 0) sred[tid >> 5] = sum;
    __syncthreads();
    if (tid == 0) {
        float s = 0.f;
        #pragma unroll
        for (int i = 0; i < 8; i++) s += sred[i];
        sred[0] = s;
    }
    __syncthreads();
    const float inv = 1.f / sred[0];

    for (int i = tid; i < SEQ; i += 256) {
        float w = g_weights[b * SEQ + i] * inv;
        g_weights[b * SEQ + i] = w;
        if (w_out) w_out[b * SEQ + i] = w;
    }
}

// ---------------------------------------------------------------------------
// Kernel 4a: context partials (split-S by NSPLIT), fp16 values (half traffic)
// ---------------------------------------------------------------------------
__global__ __launch_bounds__(256) void ctx_part_kernel()
{
    const int b  = blockIdx.x;
    const int sp = blockIdx.y;
    const int tid = threadIdx.x;
    const uint2* vp = (const uint2*)(g_values_h + (size_t)b * SEQ * DIM);
    const float* wp = g_weights + b * SEQ;

    float4 acc = make_float4(0.f, 0.f, 0.f, 0.f);
    const int s0 = sp * (SEQ / NSPLIT);
    #pragma unroll 1
    for (int s = s0; s < s0 + SEQ / NSPLIT; s += 2) {
        float w0 = wp[s], w1 = wp[s + 1];
        uint2 u0 = vp[(size_t)(s)     * 256 + tid];
        uint2 u1 = vp[(size_t)(s + 1) * 256 + tid];
        float2 a0 = __half22float2(*(const __half2*)&u0.x);
        float2 a1 = __half22float2(*(const __half2*)&u0.y);
        float2 b0 = __half22float2(*(const __half2*)&u1.x);
        float2 b1 = __half22float2(*(const __half2*)&u1.y);
        acc.x = fmaf(w0, a0.x, fmaf(w1, b0.x, acc.x));
        acc.y = fmaf(w0, a0.y, fmaf(w1, b0.y, acc.y));
        acc.z = fmaf(w0, a1.x, fmaf(w1, b1.x, acc.z));
        acc.w = fmaf(w0, a1.y, fmaf(w1, b1.y, acc.w));
    }
    ((float4*)&g_ctx_part[sp][b * DIM])[tid] = acc;
}

__global__ __launch_bounds__(256) void ctx_reduce_kernel(float* __restrict__ ctx_out)
{
    const int i = blockIdx.x * 256 + threadIdx.x;
    float acc = 0.f;
    #pragma unroll
    for (int p = 0; p < NSPLIT; p++) acc += g_ctx_part[p][i];
    ctx_out[i] = acc;
}

// ---------------------------------------------------------------------------
// Launch: inputs = query, values, W1, b1, W2, b2, V, bV
// ---------------------------------------------------------------------------
extern "C" void kernel_launch(void* const* d_in, const int* in_sizes, int n_in,
                              void* d_out, int out_size)
{
    const float* query  = (const float*)d_in[0];
    const float* values = (const float*)d_in[1];
    const float* W1     = (const float*)d_in[2];
    const float* b1     = (const float*)d_in[3];
    const float* W2     = (const float*)d_in[4];
    const float* b2     = (const float*)d_in[5];
    const float* V      = (const float*)d_in[6];
    // bV shifts every score equally -> softmax-invariant; unused.

    float* out = (float*)d_out;
    float* ctx_out = nullptr;
    float* w_out   = nullptr;
    if (out_size >= BATCH * DIM + BATCH * SEQ) {
        ctx_out = out;
        w_out   = out + BATCH * DIM;
    } else if (out_size == BATCH * SEQ) {
        w_out = out;
    } else {
        ctx_out = out;
    }

    static int smem_set = 0;
    if (!smem_set) {
        cudaFuncSetAttribute(score_kernel, cudaFuncAttributeMaxDynamicSharedMemorySize,
                             SMEM_SCORE_BYTES);
        smem_set = 1;
    }

    convert_values_kernel<<<(BATCH * SEQ * DIM) / (256 * 8), 256>>>((const float4*)values);
    transpose_w1_kernel<<<dim3(DIM / 32, UNITS / 32), 256>>>(W1);
    qproj_kernel<<<BATCH, 256>>>(query, W2, b1, b2);
    score_kernel<<<(BATCH * SEQ) / 128, 512, SMEM_SCORE_BYTES>>>(V);
    softmax_kernel<<<BATCH, 256>>>(w_out);
    if (ctx_out) {
        ctx_part_kernel<<<dim3(BATCH, NSPLIT), 256>>>();
        ctx_reduce_kernel<<<(BATCH * DIM) / 256, 256>>>(ctx_out);
    }
}

// round 10
// speedup vs baseline: 1.0270x; 1.0270x over previous
#include <cuda_runtime.h>
#include <cuda_fp16.h>
#include <stdint.h>
#include <math.h>

#define BATCH 32
#define SEQ   2048
#define DIM   1024
#define UNITS 1024

// ---------------------------------------------------------------------------
// Scratch (no device allocs allowed)
// ---------------------------------------------------------------------------
#define NSPLIT 16
__device__ __half g_values_h[BATCH * SEQ * DIM];   // fp16 copy of values (128MB)
__device__ __half g_W1T_h[UNITS * DIM];            // W1 transposed, fp16 [u][d]
__device__ float  g_qb[BATCH * UNITS];             // query@W2 + b2 + b1
__device__ float  g_scores[BATCH * SEQ];
__device__ float  g_weights[BATCH * SEQ];
__device__ float  g_ctx_part[NSPLIT][BATCH * DIM];

// ---------------------------------------------------------------------------
// PTX helpers
// ---------------------------------------------------------------------------
__device__ __forceinline__ uint32_t smem_u32(const void* p) {
    uint32_t a;
    asm("{ .reg .u64 t; cvta.to.shared.u64 t, %1; cvt.u32.u64 %0, t; }" : "=r"(a) : "l"(p));
    return a;
}
#define CP_ASYNC16(s, g) \
    asm volatile("cp.async.cg.shared.global [%0], [%1], 16;" :: "r"(s), "l"(g))
#define CP_COMMIT() asm volatile("cp.async.commit_group;" ::: "memory")
#define CP_WAIT0()  asm volatile("cp.async.wait_group 0;" ::: "memory")

// mma.sync m16n8k16 fp16 inputs, fp32 accum (baseline PTX, sm_80+)
__device__ __forceinline__ void mma_f16(float* d, const uint32_t* a, const uint32_t* b) {
    asm volatile(
        "mma.sync.aligned.m16n8k16.row.col.f32.f16.f16.f32 "
        "{%0,%1,%2,%3}, {%4,%5,%6,%7}, {%8,%9}, {%0,%1,%2,%3};"
        : "+f"(d[0]), "+f"(d[1]), "+f"(d[2]), "+f"(d[3])
        : "r"(a[0]), "r"(a[1]), "r"(a[2]), "r"(a[3]), "r"(b[0]), "r"(b[1]));
}

// ldmatrix x4 (baseline PTX, sm_75+)
__device__ __forceinline__ void ldsm_x4(uint32_t* r, uint32_t saddr) {
    asm volatile("ldmatrix.sync.aligned.m8n8.x4.shared.b16 {%0,%1,%2,%3}, [%4];"
        : "=r"(r[0]), "=r"(r[1]), "=r"(r[2]), "=r"(r[3]) : "r"(saddr));
}

// ---------------------------------------------------------------------------
// FMA-only tanh (no MUFU): abs err < ~5e-5
// ---------------------------------------------------------------------------
__device__ __forceinline__ float tanh_fast(float x) {
    float ax = fminf(fabsf(x), 10.0f);
    float t  = ax * 2.885390081777927f;
    float fn = t + 12582912.0f;
    int   n  = __float_as_int(fn) - __float_as_int(12582912.0f);
    float f  = t - (fn - 12582912.0f);
    float p  = 9.6181e-3f;
    p = fmaf(p, f, 5.5504e-2f);
    p = fmaf(p, f, 2.4022651e-1f);
    p = fmaf(p, f, 6.9314718e-1f);
    p = fmaf(p, f, 1.0f);
    float e = __int_as_float(__float_as_int(p) + (n << 23));
    float d = e + 1.0f;
    float r = __int_as_float(0x7EF311C3u - __float_as_int(d));
    r = r * fmaf(-d, r, 2.0f);
    r = r * fmaf(-d, r, 2.0f);
    float th = fmaf(-2.0f, r, 1.0f);
    return __int_as_float(__float_as_int(th) | (__float_as_int(x) & 0x80000000));
}

// ---------------------------------------------------------------------------
// Fused prep kernel: heterogeneous blocks, all three jobs run concurrently.
//   blocks [0, 32):        qproj  (g_qb = query@W2 + b1 + b2)
//   blocks [32, 1056):     transpose W1 -> g_W1T_h fp16
//   blocks [1056, 33824):  convert values -> g_values_h fp16
// ---------------------------------------------------------------------------
#define PREP_QPROJ_BLKS  BATCH
#define PREP_TRANS_BLKS  ((DIM / 32) * (UNITS / 32))            // 1024
#define PREP_CONV_BLKS   ((BATCH * SEQ * DIM) / (256 * 8))      // 32768
#define PREP_GRID        (PREP_QPROJ_BLKS + PREP_TRANS_BLKS + PREP_CONV_BLKS)

__global__ __launch_bounds__(256) void prep_kernel(
    const float* __restrict__ query, const float* __restrict__ values,
    const float* __restrict__ W1,   const float* __restrict__ b1,
    const float* __restrict__ W2,   const float* __restrict__ b2)
{
    const int tid = threadIdx.x;
    const int bid = blockIdx.x;

    if (bid < PREP_QPROJ_BLKS) {
        // ---- qproj for batch b = bid ----
        __shared__ float qrow[DIM];
        const int b = bid;
        for (int i = tid; i < DIM; i += 256)
            qrow[i] = query[b * DIM + i];
        __syncthreads();
        for (int u = tid; u < UNITS; u += 256) {
            float acc = 0.f;
            #pragma unroll 8
            for (int d = 0; d < DIM; d++)
                acc = fmaf(qrow[d], W2[d * UNITS + u], acc);
            g_qb[b * UNITS + u] = acc + b1[u] + b2[u];
        }
    } else if (bid < PREP_QPROJ_BLKS + PREP_TRANS_BLKS) {
        // ---- W1 transpose tile ----
        __shared__ float t[32][33];
        const int tile = bid - PREP_QPROJ_BLKS;
        const int d0 = (tile & 31) * 32;
        const int u0 = (tile >> 5) * 32;
        const int tx = tid & 31;
        const int ty = tid >> 5;
        #pragma unroll
        for (int i = 0; i < 4; i++) {
            int r = ty + i * 8;
            t[r][tx] = W1[(size_t)(d0 + r) * UNITS + u0 + tx];
        }
        __syncthreads();
        #pragma unroll
        for (int i = 0; i < 4; i++) {
            int r = ty + i * 8;
            g_W1T_h[(size_t)(u0 + r) * DIM + d0 + tx] = __float2half_rn(t[tx][r]);
        }
    } else {
        // ---- values fp32 -> fp16, 8 elems per thread ----
        const size_t idx = (size_t)(bid - PREP_QPROJ_BLKS - PREP_TRANS_BLKS) * 256 + tid;
        const float4* in = (const float4*)values;
        float4 v0 = in[idx * 2];
        float4 v1 = in[idx * 2 + 1];
        __half2 h0 = __floats2half2_rn(v0.x, v0.y);
        __half2 h1 = __floats2half2_rn(v0.z, v0.w);
        __half2 h2 = __floats2half2_rn(v1.x, v1.y);
        __half2 h3 = __floats2half2_rn(v1.z, v1.w);
        uint4 o;
        o.x = *(uint32_t*)&h0; o.y = *(uint32_t*)&h1;
        o.z = *(uint32_t*)&h2; o.w = *(uint32_t*)&h3;
        ((uint4*)g_values_h)[idx] = o;
    }
}

// ---------------------------------------------------------------------------
// Kernel 2: fused score GEMM via mma.sync fp16 (m16n8k16) + ldmatrix
// CTA tile 128(M) x 256(N), 4 N-passes, K chunks of 128 -> 32 flat chunks.
// 256 threads = 8 warps (2M x 4N), warp tile 64x64 (mi=4, ni=8).
// 2-stage cp.async pipeline (prefetch depth 1), one __syncthreads per chunk.
// ---------------------------------------------------------------------------
#define KC        128                  // K per chunk
#define A_PITCH_H 136                  // 272 B rows: conflict-free LDSM + cp.async
#define B_PITCH_H 136
#define A_STAGE_H (128 * A_PITCH_H)    // 17408 halfs
#define B_STAGE_H (256 * B_PITCH_H)    // 34816 halfs
#define OFF_B_H   (2 * A_STAGE_H)      // 34816 halfs
#define SMEM_HALFS (OFF_B_H + 2 * B_STAGE_H)         // 104448 halfs
#define OFF_SC_BYTES (SMEM_HALFS * 2)                // 208896
#define SMEM_SCORE_BYTES (OFF_SC_BYTES + 128 * 4)    // 209408

__device__ __forceinline__ void load_chunk(uint32_t sb, int stage, int m0, int c, int tid)
{
    const int n0 = (c >> 3) * 256;
    const int k0 = (c & 7) * KC;
    const uint32_t a_s = sb + stage * A_STAGE_H * 2;
    const uint32_t b_s = sb + (OFF_B_H + stage * B_STAGE_H) * 2;
    // A: values_h tile 128 x 128 halfs (2048 16B chunks / 256 thr = 8)
    #pragma unroll
    for (int t = 0; t < 8; t++) {
        int idx = tid + t * 256;
        int r = idx >> 4, cc = idx & 15;
        CP_ASYNC16(a_s + r * 272 + cc * 16,
                   g_values_h + (size_t)(m0 + r) * DIM + k0 + cc * 8);
    }
    // B: W1T_h tile 256 x 128 halfs (4096 chunks / 256 thr = 16)
    #pragma unroll
    for (int t = 0; t < 16; t++) {
        int idx = tid + t * 256;
        int r = idx >> 4, cc = idx & 15;
        CP_ASYNC16(b_s + r * 272 + cc * 16,
                   g_W1T_h + (size_t)(n0 + r) * DIM + k0 + cc * 8);
    }
}

__global__ __launch_bounds__(256, 1) void score_kernel(const float* __restrict__ V)
{
    extern __shared__ __align__(16) char smraw[];
    float* s_sc = (float*)(smraw + OFF_SC_BYTES);
    const uint32_t sb = smem_u32(smraw);

    const int tid  = threadIdx.x;
    const int warp = tid >> 5;
    const int lane = tid & 31;
    const int wm   = warp >> 2;          // 0..1 (M)
    const int wn   = warp & 3;           // 0..3 (N)
    const int grp  = lane >> 2;          // 0..7
    const int ctg  = lane & 3;           // 0..3
    const int m0   = blockIdx.x * 128;
    const int b    = m0 >> 11;

    // ldmatrix lane-addressing: row-in-16 and k-octet select
    const int lrow = ((lane >> 3) & 1) * 8 + (lane & 7);   // 0..15
    const int lkoc = ((lane >> 4) & 1) * 8;                // 0 or 8

    if (tid < 128) s_sc[tid] = 0.f;

    float p[4][2];
    #pragma unroll
    for (int i = 0; i < 4; i++) { p[i][0] = 0.f; p[i][1] = 0.f; }

    float acc[4][8][4];

    load_chunk(sb, 0, m0, 0, tid); CP_COMMIT();

    for (int c = 0; c < 32; c++) {
        const int stage = c & 1;
        CP_WAIT0();
        __syncthreads();
        if (c + 1 < 32) {
            load_chunk(sb, (c + 1) & 1, m0, c + 1, tid);
            CP_COMMIT();
        }

        if ((c & 7) == 0) {
            #pragma unroll
            for (int mi = 0; mi < 4; mi++)
                #pragma unroll
                for (int ni = 0; ni < 8; ni++)
                    #pragma unroll
                    for (int r = 0; r < 4; r++)
                        acc[mi][ni][r] = 0.f;
        }

        // base smem byte addresses for this stage's A / B tiles
        const uint32_t a_base = sb + stage * A_STAGE_H * 2
                              + ((wm * 64 + lrow) * A_PITCH_H + lkoc) * 2;
        const uint32_t b_base = sb + (OFF_B_H + stage * B_STAGE_H) * 2
                              + ((wn * 64 + lrow) * B_PITCH_H + lkoc) * 2;

        #pragma unroll
        for (int k16 = 0; k16 < KC / 16; k16++) {
            const int kb = k16 * 16;
            uint32_t afr[4][4], bfr[8][2];
            // A: one ldmatrix.x4 per 16-row mi tile -> afr[mi][0..3]
            #pragma unroll
            for (int mi = 0; mi < 4; mi++)
                ldsm_x4(afr[mi], a_base + (mi * 16 * A_PITCH_H + kb) * 2);
            // B: one ldmatrix.x4 per ni pair -> bfr[2p..2p+1][0..1]
            #pragma unroll
            for (int pr = 0; pr < 4; pr++) {
                uint32_t tmp[4];
                ldsm_x4(tmp, b_base + (pr * 16 * B_PITCH_H + kb) * 2);
                bfr[2 * pr][0]     = tmp[0];
                bfr[2 * pr + 1][0] = tmp[1];
                bfr[2 * pr][1]     = tmp[2];
                bfr[2 * pr + 1][1] = tmp[3];
            }
            #pragma unroll
            for (int mi = 0; mi < 4; mi++)
                #pragma unroll
                for (int ni = 0; ni < 8; ni++)
                    mma_f16(acc[mi][ni], afr[mi], bfr[ni]);
        }

        if ((c & 7) == 7) {
            // epilogue for this n-pass: tanh(acc + qb) * V (regs + gmem only)
            const int n0 = (c >> 3) * 256;
            #pragma unroll
            for (int ni = 0; ni < 8; ni++) {
                const int nloc = n0 + wn * 64 + ni * 8 + ctg * 2;
                const float2 q2 = *(const float2*)&g_qb[b * UNITS + nloc];
                const float2 v2 = *(const float2*)&V[nloc];
                #pragma unroll
                for (int mi = 0; mi < 4; mi++) {
                    p[mi][0] = fmaf(tanh_fast(acc[mi][ni][0] + q2.x), v2.x, p[mi][0]);
                    p[mi][0] = fmaf(tanh_fast(acc[mi][ni][1] + q2.y), v2.y, p[mi][0]);
                    p[mi][1] = fmaf(tanh_fast(acc[mi][ni][2] + q2.x), v2.x, p[mi][1]);
                    p[mi][1] = fmaf(tanh_fast(acc[mi][ni][3] + q2.y), v2.y, p[mi][1]);
                }
            }
        }
    }

    // reduce over quad lanes (ctg), then across the 4 n-warps via smem atomics
    #pragma unroll
    for (int mi = 0; mi < 4; mi++) {
        #pragma unroll
        for (int r = 0; r < 2; r++) {
            float v = p[mi][r];
            v += __shfl_xor_sync(0xffffffffu, v, 1);
            v += __shfl_xor_sync(0xffffffffu, v, 2);
            if (ctg == 0)
                atomicAdd(&s_sc[wm * 64 + mi * 16 + r * 8 + grp], v);
        }
    }
    __syncthreads();
    if (tid < 128) g_scores[m0 + tid] = s_sc[tid];
}

// ---------------------------------------------------------------------------
// Kernel 3: softmax over sequence axis
// ---------------------------------------------------------------------------
__global__ __launch_bounds__(256) void softmax_kernel(float* __restrict__ w_out)
{
    const int b   = blockIdx.x;
    const int tid = threadIdx.x;
    const float* sc = g_scores + b * SEQ;
    __shared__ float sred[8];

    float m = -1e30f;
    for (int i = tid; i < SEQ; i += 256) m = fmaxf(m, sc[i]);
    #pragma unroll
    for (int off = 16; off > 0; off >>= 1)
        m = fmaxf(m, __shfl_xor_sync(0xffffffffu, m, off));
    if ((tid & 31) == 0) sred[tid >> 5] = m;
    __syncthreads();
    if (tid == 0) {
        float mm = sred[0];
        #pragma unroll
        for (int i = 1; i < 8; i++) mm = fmaxf(mm, sred[i]);
        sred[0] = mm;
    }
    __syncthreads();
    const float bm = sred[0];
    __syncthreads();

    float sum = 0.f;
    for (int i = tid; i < SEQ; i += 256) {
        float e = __expf(sc[i] - bm);
        g_weights[b * SEQ + i] = e;
        sum += e;
    }
    #pragma unroll
    for (int off = 16; off > 0; off >>= 1)
        sum += __shfl_xor_sync(0xffffffffu, sum, off);
    if ((tid & 31) == 0) sred[tid >> 5] = sum;
    __syncthreads();
    if (tid == 0) {
        float s = 0.f;
        #pragma unroll
        for (int i = 0; i < 8; i++) s += sred[i];
        sred[0] = s;
    }
    __syncthreads();
    const float inv = 1.f / sred[0];

    for (int i = tid; i < SEQ; i += 256) {
        float w = g_weights[b * SEQ + i] * inv;
        g_weights[b * SEQ + i] = w;
        if (w_out) w_out[b * SEQ + i] = w;
    }
}

// ---------------------------------------------------------------------------
// Kernel 4a: context partials (split-S by NSPLIT), fp16 values (half traffic)
// ---------------------------------------------------------------------------
__global__ __launch_bounds__(256) void ctx_part_kernel()
{
    const int b  = blockIdx.x;
    const int sp = blockIdx.y;
    const int tid = threadIdx.x;
    const uint2* vp = (const uint2*)(g_values_h + (size_t)b * SEQ * DIM);
    const float* wp = g_weights + b * SEQ;

    float4 acc = make_float4(0.f, 0.f, 0.f, 0.f);
    const int s0 = sp * (SEQ / NSPLIT);
    #pragma unroll 1
    for (int s = s0; s < s0 + SEQ / NSPLIT; s += 2) {
        float w0 = wp[s], w1 = wp[s + 1];
        uint2 u0 = vp[(size_t)(s)     * 256 + tid];
        uint2 u1 = vp[(size_t)(s + 1) * 256 + tid];
        float2 a0 = __half22float2(*(const __half2*)&u0.x);
        float2 a1 = __half22float2(*(const __half2*)&u0.y);
        float2 b0 = __half22float2(*(const __half2*)&u1.x);
        float2 b1 = __half22float2(*(const __half2*)&u1.y);
        acc.x = fmaf(w0, a0.x, fmaf(w1, b0.x, acc.x));
        acc.y = fmaf(w0, a0.y, fmaf(w1, b0.y, acc.y));
        acc.z = fmaf(w0, a1.x, fmaf(w1, b1.x, acc.z));
        acc.w = fmaf(w0, a1.y, fmaf(w1, b1.y, acc.w));
    }
    ((float4*)&g_ctx_part[sp][b * DIM])[tid] = acc;
}

__global__ __launch_bounds__(256) void ctx_reduce_kernel(float* __restrict__ ctx_out)
{
    const int i = blockIdx.x * 256 + threadIdx.x;
    float acc = 0.f;
    #pragma unroll
    for (int p = 0; p < NSPLIT; p++) acc += g_ctx_part[p][i];
    ctx_out[i] = acc;
}

// ---------------------------------------------------------------------------
// Launch: inputs = query, values, W1, b1, W2, b2, V, bV
// ---------------------------------------------------------------------------
extern "C" void kernel_launch(void* const* d_in, const int* in_sizes, int n_in,
                              void* d_out, int out_size)
{
    const float* query  = (const float*)d_in[0];
    const float* values = (const float*)d_in[1];
    const float* W1     = (const float*)d_in[2];
    const float* b1     = (const float*)d_in[3];
    const float* W2     = (const float*)d_in[4];
    const float* b2     = (const float*)d_in[5];
    const float* V      = (const float*)d_in[6];
    // bV shifts every score equally -> softmax-invariant; unused.

    float* out = (float*)d_out;
    float* ctx_out = nullptr;
    float* w_out   = nullptr;
    if (out_size >= BATCH * DIM + BATCH * SEQ) {
        ctx_out = out;
        w_out   = out + BATCH * DIM;
    } else if (out_size == BATCH * SEQ) {
        w_out = out;
    } else {
        ctx_out = out;
    }

    static int smem_set = 0;
    if (!smem_set) {
        cudaFuncSetAttribute(score_kernel, cudaFuncAttributeMaxDynamicSharedMemorySize,
                             SMEM_SCORE_BYTES);
        smem_set = 1;
    }

    prep_kernel<<<PREP_GRID, 256>>>(query, values, W1, b1, W2, b2);
    score_kernel<<<(BATCH * SEQ) / 128, 256, SMEM_SCORE_BYTES>>>(V);
    softmax_kernel<<<BATCH, 256>>>(w_out);
    if (ctx_out) {
        ctx_part_kernel<<<dim3(BATCH, NSPLIT), 256>>>();
        ctx_reduce_kernel<<<(BATCH * DIM) / 256, 256>>>(ctx_out);
    }
}

// round 11
// speedup vs baseline: 1.0469x; 1.0194x over previous
#include <cuda_runtime.h>
#include <cuda_fp16.h>
#include <stdint.h>
#include <math.h>

#define BATCH 32
#define SEQ   2048
#define DIM   1024
#define UNITS 1024

// ---------------------------------------------------------------------------
// Scratch (no device allocs allowed)
// ---------------------------------------------------------------------------
#define NSPLIT 16
__device__ __half g_values_h[BATCH * SEQ * DIM];   // fp16 copy of values (128MB)
__device__ __half g_W1T_h[UNITS * DIM];            // W1 transposed, fp16 [u][d]
__device__ float  g_qb[BATCH * UNITS];             // query@W2 + b2 + b1
__device__ float  g_scores_part[2][BATCH * SEQ];   // split-N partial scores
__device__ float  g_weights[BATCH * SEQ];
__device__ float  g_ctx_part[NSPLIT][BATCH * DIM];

// ---------------------------------------------------------------------------
// PTX helpers
// ---------------------------------------------------------------------------
__device__ __forceinline__ uint32_t smem_u32(const void* p) {
    uint32_t a;
    asm("{ .reg .u64 t; cvta.to.shared.u64 t, %1; cvt.u32.u64 %0, t; }" : "=r"(a) : "l"(p));
    return a;
}
#define CP_ASYNC16(s, g) \
    asm volatile("cp.async.cg.shared.global [%0], [%1], 16;" :: "r"(s), "l"(g))
#define CP_COMMIT() asm volatile("cp.async.commit_group;" ::: "memory")
#define CP_WAIT0()  asm volatile("cp.async.wait_group 0;" ::: "memory")

// mma.sync m16n8k16 fp16 inputs, fp32 accum (baseline PTX, sm_80+)
__device__ __forceinline__ void mma_f16(float* d, const uint32_t* a, const uint32_t* b) {
    asm volatile(
        "mma.sync.aligned.m16n8k16.row.col.f32.f16.f16.f32 "
        "{%0,%1,%2,%3}, {%4,%5,%6,%7}, {%8,%9}, {%0,%1,%2,%3};"
        : "+f"(d[0]), "+f"(d[1]), "+f"(d[2]), "+f"(d[3])
        : "r"(a[0]), "r"(a[1]), "r"(a[2]), "r"(a[3]), "r"(b[0]), "r"(b[1]));
}

// ldmatrix x4 (baseline PTX, sm_75+)
__device__ __forceinline__ void ldsm_x4(uint32_t* r, uint32_t saddr) {
    asm volatile("ldmatrix.sync.aligned.m8n8.x4.shared.b16 {%0,%1,%2,%3}, [%4];"
        : "=r"(r[0]), "=r"(r[1]), "=r"(r[2]), "=r"(r[3]) : "r"(saddr));
}

// ---------------------------------------------------------------------------
// FMA-only tanh (no MUFU): abs err < ~5e-5
// ---------------------------------------------------------------------------
__device__ __forceinline__ float tanh_fast(float x) {
    float ax = fminf(fabsf(x), 10.0f);
    float t  = ax * 2.885390081777927f;
    float fn = t + 12582912.0f;
    int   n  = __float_as_int(fn) - __float_as_int(12582912.0f);
    float f  = t - (fn - 12582912.0f);
    float p  = 9.6181e-3f;
    p = fmaf(p, f, 5.5504e-2f);
    p = fmaf(p, f, 2.4022651e-1f);
    p = fmaf(p, f, 6.9314718e-1f);
    p = fmaf(p, f, 1.0f);
    float e = __int_as_float(__float_as_int(p) + (n << 23));
    float d = e + 1.0f;
    float r = __int_as_float(0x7EF311C3u - __float_as_int(d));
    r = r * fmaf(-d, r, 2.0f);
    r = r * fmaf(-d, r, 2.0f);
    float th = fmaf(-2.0f, r, 1.0f);
    return __int_as_float(__float_as_int(th) | (__float_as_int(x) & 0x80000000));
}

// ---------------------------------------------------------------------------
// Fused prep kernel: heterogeneous blocks, all three jobs run concurrently.
// ---------------------------------------------------------------------------
#define PREP_QPROJ_BLKS  BATCH
#define PREP_TRANS_BLKS  ((DIM / 32) * (UNITS / 32))            // 1024
#define PREP_CONV_BLKS   ((BATCH * SEQ * DIM) / (256 * 8))      // 32768
#define PREP_GRID        (PREP_QPROJ_BLKS + PREP_TRANS_BLKS + PREP_CONV_BLKS)

__global__ __launch_bounds__(256) void prep_kernel(
    const float* __restrict__ query, const float* __restrict__ values,
    const float* __restrict__ W1,   const float* __restrict__ b1,
    const float* __restrict__ W2,   const float* __restrict__ b2)
{
    const int tid = threadIdx.x;
    const int bid = blockIdx.x;

    if (bid < PREP_QPROJ_BLKS) {
        __shared__ float qrow[DIM];
        const int b = bid;
        for (int i = tid; i < DIM; i += 256)
            qrow[i] = query[b * DIM + i];
        __syncthreads();
        for (int u = tid; u < UNITS; u += 256) {
            float acc = 0.f;
            #pragma unroll 8
            for (int d = 0; d < DIM; d++)
                acc = fmaf(qrow[d], W2[d * UNITS + u], acc);
            g_qb[b * UNITS + u] = acc + b1[u] + b2[u];
        }
    } else if (bid < PREP_QPROJ_BLKS + PREP_TRANS_BLKS) {
        __shared__ float t[32][33];
        const int tile = bid - PREP_QPROJ_BLKS;
        const int d0 = (tile & 31) * 32;
        const int u0 = (tile >> 5) * 32;
        const int tx = tid & 31;
        const int ty = tid >> 5;
        #pragma unroll
        for (int i = 0; i < 4; i++) {
            int r = ty + i * 8;
            t[r][tx] = W1[(size_t)(d0 + r) * UNITS + u0 + tx];
        }
        __syncthreads();
        #pragma unroll
        for (int i = 0; i < 4; i++) {
            int r = ty + i * 8;
            g_W1T_h[(size_t)(u0 + r) * DIM + d0 + tx] = __float2half_rn(t[tx][r]);
        }
    } else {
        const size_t idx = (size_t)(bid - PREP_QPROJ_BLKS - PREP_TRANS_BLKS) * 256 + tid;
        const float4* in = (const float4*)values;
        float4 v0 = in[idx * 2];
        float4 v1 = in[idx * 2 + 1];
        __half2 h0 = __floats2half2_rn(v0.x, v0.y);
        __half2 h1 = __floats2half2_rn(v0.z, v0.w);
        __half2 h2 = __floats2half2_rn(v1.x, v1.y);
        __half2 h3 = __floats2half2_rn(v1.z, v1.w);
        uint4 o;
        o.x = *(uint32_t*)&h0; o.y = *(uint32_t*)&h1;
        o.z = *(uint32_t*)&h2; o.w = *(uint32_t*)&h3;
        ((uint4*)g_values_h)[idx] = o;
    }
}

// ---------------------------------------------------------------------------
// Kernel 2: fused score GEMM via mma.sync fp16 (m16n8k16) + ldmatrix
// Split-N: each CTA = 128(M) rows x 512(N) units (one N-half), 2 n-passes,
// K chunks of 128 -> 16 flat chunks. Grid = 1024 (512 row tiles x 2 halves).
// 256 threads = 8 warps (2M x 4N), warp tile 64x64 (mi=4, ni=8).
// 2-stage cp.async pipeline, one __syncthreads per chunk.
// ---------------------------------------------------------------------------
#define KC        128                  // K per chunk
#define A_PITCH_H 136                  // 272 B rows: conflict-free LDSM + cp.async
#define B_PITCH_H 136
#define A_STAGE_H (128 * A_PITCH_H)    // 17408 halfs
#define B_STAGE_H (256 * B_PITCH_H)    // 34816 halfs
#define OFF_B_H   (2 * A_STAGE_H)      // 34816 halfs
#define SMEM_HALFS (OFF_B_H + 2 * B_STAGE_H)         // 104448 halfs
#define OFF_SC_BYTES (SMEM_HALFS * 2)                // 208896
#define SMEM_SCORE_BYTES (OFF_SC_BYTES + 128 * 4)    // 209408

__device__ __forceinline__ void load_chunk(uint32_t sb, int stage, int m0, int nbase,
                                           int c, int tid)
{
    const int n0 = nbase + (c >> 3) * 256;
    const int k0 = (c & 7) * KC;
    const uint32_t a_s = sb + stage * A_STAGE_H * 2;
    const uint32_t b_s = sb + (OFF_B_H + stage * B_STAGE_H) * 2;
    // A: values_h tile 128 x 128 halfs (2048 16B chunks / 256 thr = 8)
    #pragma unroll
    for (int t = 0; t < 8; t++) {
        int idx = tid + t * 256;
        int r = idx >> 4, cc = idx & 15;
        CP_ASYNC16(a_s + r * 272 + cc * 16,
                   g_values_h + (size_t)(m0 + r) * DIM + k0 + cc * 8);
    }
    // B: W1T_h tile 256 x 128 halfs (4096 chunks / 256 thr = 16)
    #pragma unroll
    for (int t = 0; t < 16; t++) {
        int idx = tid + t * 256;
        int r = idx >> 4, cc = idx & 15;
        CP_ASYNC16(b_s + r * 272 + cc * 16,
                   g_W1T_h + (size_t)(n0 + r) * DIM + k0 + cc * 8);
    }
}

__global__ __launch_bounds__(256, 1) void score_kernel(const float* __restrict__ V)
{
    extern __shared__ __align__(16) char smraw[];
    float* s_sc = (float*)(smraw + OFF_SC_BYTES);
    const uint32_t sb = smem_u32(smraw);

    const int tid  = threadIdx.x;
    const int warp = tid >> 5;
    const int lane = tid & 31;
    const int wm   = warp >> 2;          // 0..1 (M)
    const int wn   = warp & 3;           // 0..3 (N)
    const int grp  = lane >> 2;          // 0..7
    const int ctg  = lane & 3;           // 0..3
    const int nhalf = blockIdx.x & 1;                // 0 or 1
    const int m0    = (blockIdx.x >> 1) * 128;
    const int nbase = nhalf * 512;
    const int b     = m0 >> 11;

    // ldmatrix lane-addressing: row-in-16 and k-octet select
    const int lrow = ((lane >> 3) & 1) * 8 + (lane & 7);   // 0..15
    const int lkoc = ((lane >> 4) & 1) * 8;                // 0 or 8

    if (tid < 128) s_sc[tid] = 0.f;

    float p[4][2];
    #pragma unroll
    for (int i = 0; i < 4; i++) { p[i][0] = 0.f; p[i][1] = 0.f; }

    float acc[4][8][4];

    load_chunk(sb, 0, m0, nbase, 0, tid); CP_COMMIT();

    for (int c = 0; c < 16; c++) {
        const int stage = c & 1;
        CP_WAIT0();
        __syncthreads();
        if (c + 1 < 16) {
            load_chunk(sb, (c + 1) & 1, m0, nbase, c + 1, tid);
            CP_COMMIT();
        }

        if ((c & 7) == 0) {
            #pragma unroll
            for (int mi = 0; mi < 4; mi++)
                #pragma unroll
                for (int ni = 0; ni < 8; ni++)
                    #pragma unroll
                    for (int r = 0; r < 4; r++)
                        acc[mi][ni][r] = 0.f;
        }

        const uint32_t a_base = sb + stage * A_STAGE_H * 2
                              + ((wm * 64 + lrow) * A_PITCH_H + lkoc) * 2;
        const uint32_t b_base = sb + (OFF_B_H + stage * B_STAGE_H) * 2
                              + ((wn * 64 + lrow) * B_PITCH_H + lkoc) * 2;

        #pragma unroll
        for (int k16 = 0; k16 < KC / 16; k16++) {
            const int kb = k16 * 16;
            uint32_t afr[4][4], bfr[8][2];
            #pragma unroll
            for (int mi = 0; mi < 4; mi++)
                ldsm_x4(afr[mi], a_base + (mi * 16 * A_PITCH_H + kb) * 2);
            #pragma unroll
            for (int pr = 0; pr < 4; pr++) {
                uint32_t tmp[4];
                ldsm_x4(tmp, b_base + (pr * 16 * B_PITCH_H + kb) * 2);
                bfr[2 * pr][0]     = tmp[0];
                bfr[2 * pr + 1][0] = tmp[1];
                bfr[2 * pr][1]     = tmp[2];
                bfr[2 * pr + 1][1] = tmp[3];
            }
            #pragma unroll
            for (int mi = 0; mi < 4; mi++)
                #pragma unroll
                for (int ni = 0; ni < 8; ni++)
                    mma_f16(acc[mi][ni], afr[mi], bfr[ni]);
        }

        if ((c & 7) == 7) {
            // epilogue for this n-pass: tanh(acc + qb) * V (regs + gmem only)
            const int n0 = nbase + (c >> 3) * 256;
            #pragma unroll
            for (int ni = 0; ni < 8; ni++) {
                const int nloc = n0 + wn * 64 + ni * 8 + ctg * 2;
                const float2 q2 = *(const float2*)&g_qb[b * UNITS + nloc];
                const float2 v2 = *(const float2*)&V[nloc];
                #pragma unroll
                for (int mi = 0; mi < 4; mi++) {
                    p[mi][0] = fmaf(tanh_fast(acc[mi][ni][0] + q2.x), v2.x, p[mi][0]);
                    p[mi][0] = fmaf(tanh_fast(acc[mi][ni][1] + q2.y), v2.y, p[mi][0]);
                    p[mi][1] = fmaf(tanh_fast(acc[mi][ni][2] + q2.x), v2.x, p[mi][1]);
                    p[mi][1] = fmaf(tanh_fast(acc[mi][ni][3] + q2.y), v2.y, p[mi][1]);
                }
            }
        }
    }

    // reduce over quad lanes (ctg), then across the 4 n-warps via smem atomics
    #pragma unroll
    for (int mi = 0; mi < 4; mi++) {
        #pragma unroll
        for (int r = 0; r < 2; r++) {
            float v = p[mi][r];
            v += __shfl_xor_sync(0xffffffffu, v, 1);
            v += __shfl_xor_sync(0xffffffffu, v, 2);
            if (ctg == 0)
                atomicAdd(&s_sc[wm * 64 + mi * 16 + r * 8 + grp], v);
        }
    }
    __syncthreads();
    if (tid < 128) g_scores_part[nhalf][m0 + tid] = s_sc[tid];
}

// ---------------------------------------------------------------------------
// Kernel 3: softmax over sequence axis (sums the two N-half partials)
// ---------------------------------------------------------------------------
__global__ __launch_bounds__(256) void softmax_kernel(float* __restrict__ w_out)
{
    const int b   = blockIdx.x;
    const int tid = threadIdx.x;
    const float* sc0 = g_scores_part[0] + b * SEQ;
    const float* sc1 = g_scores_part[1] + b * SEQ;
    __shared__ float sred[8];

    float m = -1e30f;
    for (int i = tid; i < SEQ; i += 256) m = fmaxf(m, sc0[i] + sc1[i]);
    #pragma unroll
    for (int off = 16; off > 0; off >>= 1)
        m = fmaxf(m, __shfl_xor_sync(0xffffffffu, m, off));
    if ((tid & 31) == 0) sred[tid >> 5] = m;
    __syncthreads();
    if (tid == 0) {
        float mm = sred[0];
        #pragma unroll
        for (int i = 1; i < 8; i++) mm = fmaxf(mm, sred[i]);
        sred[0] = mm;
    }
    __syncthreads();
    const float bm = sred[0];
    __syncthreads();

    float sum = 0.f;
    for (int i = tid; i < SEQ; i += 256) {
        float e = __expf(sc0[i] + sc1[i] - bm);
        g_weights[b * SEQ + i] = e;
        sum += e;
    }
    #pragma unroll
    for (int off = 16; off > 0; off >>= 1)
        sum += __shfl_xor_sync(0xffffffffu, sum, off);
    if ((tid & 31) == 0) sred[tid >> 5] = sum;
    __syncthreads();
    if (tid == 0) {
        float s = 0.f;
        #pragma unroll
        for (int i = 0; i < 8; i++) s += sred[i];
        sred[0] = s;
    }
    __syncthreads();
    const float inv = 1.f / sred[0];

    for (int i = tid; i < SEQ; i += 256) {
        float w = g_weights[b * SEQ + i] * inv;
        g_weights[b * SEQ + i] = w;
        if (w_out) w_out[b * SEQ + i] = w;
    }
}

// ---------------------------------------------------------------------------
// Kernel 4a: context partials (split-S by NSPLIT), fp16 values (half traffic)
// ---------------------------------------------------------------------------
__global__ __launch_bounds__(256) void ctx_part_kernel()
{
    const int b  = blockIdx.x;
    const int sp = blockIdx.y;
    const int tid = threadIdx.x;
    const uint2* vp = (const uint2*)(g_values_h + (size_t)b * SEQ * DIM);
    const float* wp = g_weights + b * SEQ;

    float4 acc = make_float4(0.f, 0.f, 0.f, 0.f);
    const int s0 = sp * (SEQ / NSPLIT);
    #pragma unroll 1
    for (int s = s0; s < s0 + SEQ / NSPLIT; s += 2) {
        float w0 = wp[s], w1 = wp[s + 1];
        uint2 u0 = vp[(size_t)(s)     * 256 + tid];
        uint2 u1 = vp[(size_t)(s + 1) * 256 + tid];
        float2 a0 = __half22float2(*(const __half2*)&u0.x);
        float2 a1 = __half22float2(*(const __half2*)&u0.y);
        float2 b0 = __half22float2(*(const __half2*)&u1.x);
        float2 b1 = __half22float2(*(const __half2*)&u1.y);
        acc.x = fmaf(w0, a0.x, fmaf(w1, b0.x, acc.x));
        acc.y = fmaf(w0, a0.y, fmaf(w1, b0.y, acc.y));
        acc.z = fmaf(w0, a1.x, fmaf(w1, b1.x, acc.z));
        acc.w = fmaf(w0, a1.y, fmaf(w1, b1.y, acc.w));
    }
    ((float4*)&g_ctx_part[sp][b * DIM])[tid] = acc;
}

__global__ __launch_bounds__(256) void ctx_reduce_kernel(float* __restrict__ ctx_out)
{
    const int i = blockIdx.x * 256 + threadIdx.x;
    float acc = 0.f;
    #pragma unroll
    for (int p = 0; p < NSPLIT; p++) acc += g_ctx_part[p][i];
    ctx_out[i] = acc;
}

// ---------------------------------------------------------------------------
// Launch: inputs = query, values, W1, b1, W2, b2, V, bV
// ---------------------------------------------------------------------------
extern "C" void kernel_launch(void* const* d_in, const int* in_sizes, int n_in,
                              void* d_out, int out_size)
{
    const float* query  = (const float*)d_in[0];
    const float* values = (const float*)d_in[1];
    const float* W1     = (const float*)d_in[2];
    const float* b1     = (const float*)d_in[3];
    const float* W2     = (const float*)d_in[4];
    const float* b2     = (const float*)d_in[5];
    const float* V      = (const float*)d_in[6];
    // bV shifts every score equally -> softmax-invariant; unused.

    float* out = (float*)d_out;
    float* ctx_out = nullptr;
    float* w_out   = nullptr;
    if (out_size >= BATCH * DIM + BATCH * SEQ) {
        ctx_out = out;
        w_out   = out + BATCH * DIM;
    } else if (out_size == BATCH * SEQ) {
        w_out = out;
    } else {
        ctx_out = out;
    }

    static int smem_set = 0;
    if (!smem_set) {
        cudaFuncSetAttribute(score_kernel, cudaFuncAttributeMaxDynamicSharedMemorySize,
                             SMEM_SCORE_BYTES);
        smem_set = 1;
    }

    prep_kernel<<<PREP_GRID, 256>>>(query, values, W1, b1, W2, b2);
    score_kernel<<<(BATCH * SEQ) / 128 * 2, 256, SMEM_SCORE_BYTES>>>(V);
    softmax_kernel<<<BATCH, 256>>>(w_out);
    if (ctx_out) {
        ctx_part_kernel<<<dim3(BATCH, NSPLIT), 256>>>();
        ctx_reduce_kernel<<<(BATCH * DIM) / 256, 256>>>(ctx_out);
    }
}

// round 12
// speedup vs baseline: 1.1296x; 1.0789x over previous
#include <cuda_runtime.h>
#include <cuda_fp16.h>
#include <stdint.h>
#include <math.h>

#define BATCH 32
#define SEQ   2048
#define DIM   1024
#define UNITS 1024

// ---------------------------------------------------------------------------
// Scratch (no device allocs allowed)
// ---------------------------------------------------------------------------
#define NSPLIT 32
__device__ __half g_values_h[BATCH * SEQ * DIM];   // fp16 copy of values (128MB)
__device__ __half g_W1T_h[UNITS * DIM];            // W1 transposed, fp16 [u][d]
__device__ float  g_qb[BATCH * UNITS];             // query@W2 + b2 + b1
__device__ float  g_scores_part[2][BATCH * SEQ];   // split-N partial scores
__device__ float  g_ctx_part[NSPLIT][BATCH * DIM];

// ---------------------------------------------------------------------------
// PTX helpers
// ---------------------------------------------------------------------------
__device__ __forceinline__ uint32_t smem_u32(const void* p) {
    uint32_t a;
    asm("{ .reg .u64 t; cvta.to.shared.u64 t, %1; cvt.u32.u64 %0, t; }" : "=r"(a) : "l"(p));
    return a;
}
#define CP_ASYNC16(s, g) \
    asm volatile("cp.async.cg.shared.global [%0], [%1], 16;" :: "r"(s), "l"(g))
#define CP_COMMIT() asm volatile("cp.async.commit_group;" ::: "memory")
#define CP_WAIT0()  asm volatile("cp.async.wait_group 0;" ::: "memory")

// mma.sync m16n8k16 fp16 inputs, fp32 accum (baseline PTX, sm_80+)
__device__ __forceinline__ void mma_f16(float* d, const uint32_t* a, const uint32_t* b) {
    asm volatile(
        "mma.sync.aligned.m16n8k16.row.col.f32.f16.f16.f32 "
        "{%0,%1,%2,%3}, {%4,%5,%6,%7}, {%8,%9}, {%0,%1,%2,%3};"
        : "+f"(d[0]), "+f"(d[1]), "+f"(d[2]), "+f"(d[3])
        : "r"(a[0]), "r"(a[1]), "r"(a[2]), "r"(a[3]), "r"(b[0]), "r"(b[1]));
}

// ldmatrix x4 (baseline PTX, sm_75+)
__device__ __forceinline__ void ldsm_x4(uint32_t* r, uint32_t saddr) {
    asm volatile("ldmatrix.sync.aligned.m8n8.x4.shared.b16 {%0,%1,%2,%3}, [%4];"
        : "=r"(r[0]), "=r"(r[1]), "=r"(r[2]), "=r"(r[3]) : "r"(saddr));
}

// ---------------------------------------------------------------------------
// FMA-only tanh (no MUFU): abs err < ~5e-5
// ---------------------------------------------------------------------------
__device__ __forceinline__ float tanh_fast(float x) {
    float ax = fminf(fabsf(x), 10.0f);
    float t  = ax * 2.885390081777927f;
    float fn = t + 12582912.0f;
    int   n  = __float_as_int(fn) - __float_as_int(12582912.0f);
    float f  = t - (fn - 12582912.0f);
    float p  = 9.6181e-3f;
    p = fmaf(p, f, 5.5504e-2f);
    p = fmaf(p, f, 2.4022651e-1f);
    p = fmaf(p, f, 6.9314718e-1f);
    p = fmaf(p, f, 1.0f);
    float e = __int_as_float(__float_as_int(p) + (n << 23));
    float d = e + 1.0f;
    float r = __int_as_float(0x7EF311C3u - __float_as_int(d));
    r = r * fmaf(-d, r, 2.0f);
    r = r * fmaf(-d, r, 2.0f);
    float th = fmaf(-2.0f, r, 1.0f);
    return __int_as_float(__float_as_int(th) | (__float_as_int(x) & 0x80000000));
}

// ---------------------------------------------------------------------------
// Fused prep kernel: heterogeneous blocks, all three jobs run concurrently.
// ---------------------------------------------------------------------------
#define PREP_QPROJ_BLKS  BATCH
#define PREP_TRANS_BLKS  ((DIM / 32) * (UNITS / 32))            // 1024
#define PREP_CONV_BLKS   ((BATCH * SEQ * DIM) / (256 * 8))      // 32768
#define PREP_GRID        (PREP_QPROJ_BLKS + PREP_TRANS_BLKS + PREP_CONV_BLKS)

__global__ __launch_bounds__(256) void prep_kernel(
    const float* __restrict__ query, const float* __restrict__ values,
    const float* __restrict__ W1,   const float* __restrict__ b1,
    const float* __restrict__ W2,   const float* __restrict__ b2)
{
    const int tid = threadIdx.x;
    const int bid = blockIdx.x;

    if (bid < PREP_QPROJ_BLKS) {
        __shared__ float qrow[DIM];
        const int b = bid;
        for (int i = tid; i < DIM; i += 256)
            qrow[i] = query[b * DIM + i];
        __syncthreads();
        for (int u = tid; u < UNITS; u += 256) {
            float acc = 0.f;
            #pragma unroll 8
            for (int d = 0; d < DIM; d++)
                acc = fmaf(qrow[d], W2[d * UNITS + u], acc);
            g_qb[b * UNITS + u] = acc + b1[u] + b2[u];
        }
    } else if (bid < PREP_QPROJ_BLKS + PREP_TRANS_BLKS) {
        __shared__ float t[32][33];
        const int tile = bid - PREP_QPROJ_BLKS;
        const int d0 = (tile & 31) * 32;
        const int u0 = (tile >> 5) * 32;
        const int tx = tid & 31;
        const int ty = tid >> 5;
        #pragma unroll
        for (int i = 0; i < 4; i++) {
            int r = ty + i * 8;
            t[r][tx] = W1[(size_t)(d0 + r) * UNITS + u0 + tx];
        }
        __syncthreads();
        #pragma unroll
        for (int i = 0; i < 4; i++) {
            int r = ty + i * 8;
            g_W1T_h[(size_t)(u0 + r) * DIM + d0 + tx] = __float2half_rn(t[tx][r]);
        }
    } else {
        const size_t idx = (size_t)(bid - PREP_QPROJ_BLKS - PREP_TRANS_BLKS) * 256 + tid;
        const float4* in = (const float4*)values;
        float4 v0 = in[idx * 2];
        float4 v1 = in[idx * 2 + 1];
        __half2 h0 = __floats2half2_rn(v0.x, v0.y);
        __half2 h1 = __floats2half2_rn(v0.z, v0.w);
        __half2 h2 = __floats2half2_rn(v1.x, v1.y);
        __half2 h3 = __floats2half2_rn(v1.z, v1.w);
        uint4 o;
        o.x = *(uint32_t*)&h0; o.y = *(uint32_t*)&h1;
        o.z = *(uint32_t*)&h2; o.w = *(uint32_t*)&h3;
        ((uint4*)g_values_h)[idx] = o;
    }
}

// ---------------------------------------------------------------------------
// Kernel 2: fused score GEMM via mma.sync fp16 (m16n8k16) + ldmatrix
// Split-N: each CTA = 128(M) rows x 512(N) units (one N-half), 2 n-passes,
// K chunks of 128 -> 16 flat chunks. Grid = 1024 (512 row tiles x 2 halves).
// 256 threads = 8 warps (2M x 4N), warp tile 64x64 (mi=4, ni=8).
// 2-stage cp.async pipeline, one __syncthreads per chunk.
// ---------------------------------------------------------------------------
#define KC        128                  // K per chunk
#define A_PITCH_H 136                  // 272 B rows: conflict-free LDSM + cp.async
#define B_PITCH_H 136
#define A_STAGE_H (128 * A_PITCH_H)    // 17408 halfs
#define B_STAGE_H (256 * B_PITCH_H)    // 34816 halfs
#define OFF_B_H   (2 * A_STAGE_H)      // 34816 halfs
#define SMEM_HALFS (OFF_B_H + 2 * B_STAGE_H)         // 104448 halfs
#define OFF_SC_BYTES (SMEM_HALFS * 2)                // 208896
#define SMEM_SCORE_BYTES (OFF_SC_BYTES + 128 * 4)    // 209408

__device__ __forceinline__ void load_chunk(uint32_t sb, int stage, int m0, int nbase,
                                           int c, int tid)
{
    const int n0 = nbase + (c >> 3) * 256;
    const int k0 = (c & 7) * KC;
    const uint32_t a_s = sb + stage * A_STAGE_H * 2;
    const uint32_t b_s = sb + (OFF_B_H + stage * B_STAGE_H) * 2;
    // A: values_h tile 128 x 128 halfs (2048 16B chunks / 256 thr = 8)
    #pragma unroll
    for (int t = 0; t < 8; t++) {
        int idx = tid + t * 256;
        int r = idx >> 4, cc = idx & 15;
        CP_ASYNC16(a_s + r * 272 + cc * 16,
                   g_values_h + (size_t)(m0 + r) * DIM + k0 + cc * 8);
    }
    // B: W1T_h tile 256 x 128 halfs (4096 chunks / 256 thr = 16)
    #pragma unroll
    for (int t = 0; t < 16; t++) {
        int idx = tid + t * 256;
        int r = idx >> 4, cc = idx & 15;
        CP_ASYNC16(b_s + r * 272 + cc * 16,
                   g_W1T_h + (size_t)(n0 + r) * DIM + k0 + cc * 8);
    }
}

__global__ __launch_bounds__(256, 1) void score_kernel(const float* __restrict__ V)
{
    extern __shared__ __align__(16) char smraw[];
    float* s_sc = (float*)(smraw + OFF_SC_BYTES);
    const uint32_t sb = smem_u32(smraw);

    const int tid  = threadIdx.x;
    const int warp = tid >> 5;
    const int lane = tid & 31;
    const int wm   = warp >> 2;          // 0..1 (M)
    const int wn   = warp & 3;           // 0..3 (N)
    const int grp  = lane >> 2;          // 0..7
    const int ctg  = lane & 3;           // 0..3
    const int nhalf = blockIdx.x & 1;                // 0 or 1
    const int m0    = (blockIdx.x >> 1) * 128;
    const int nbase = nhalf * 512;
    const int b     = m0 >> 11;

    const int lrow = ((lane >> 3) & 1) * 8 + (lane & 7);   // 0..15
    const int lkoc = ((lane >> 4) & 1) * 8;                // 0 or 8

    if (tid < 128) s_sc[tid] = 0.f;

    float p[4][2];
    #pragma unroll
    for (int i = 0; i < 4; i++) { p[i][0] = 0.f; p[i][1] = 0.f; }

    float acc[4][8][4];

    load_chunk(sb, 0, m0, nbase, 0, tid); CP_COMMIT();

    for (int c = 0; c < 16; c++) {
        const int stage = c & 1;
        CP_WAIT0();
        __syncthreads();
        if (c + 1 < 16) {
            load_chunk(sb, (c + 1) & 1, m0, nbase, c + 1, tid);
            CP_COMMIT();
        }

        if ((c & 7) == 0) {
            #pragma unroll
            for (int mi = 0; mi < 4; mi++)
                #pragma unroll
                for (int ni = 0; ni < 8; ni++)
                    #pragma unroll
                    for (int r = 0; r < 4; r++)
                        acc[mi][ni][r] = 0.f;
        }

        const uint32_t a_base = sb + stage * A_STAGE_H * 2
                              + ((wm * 64 + lrow) * A_PITCH_H + lkoc) * 2;
        const uint32_t b_base = sb + (OFF_B_H + stage * B_STAGE_H) * 2
                              + ((wn * 64 + lrow) * B_PITCH_H + lkoc) * 2;

        #pragma unroll
        for (int k16 = 0; k16 < KC / 16; k16++) {
            const int kb = k16 * 16;
            uint32_t afr[4][4], bfr[8][2];
            #pragma unroll
            for (int mi = 0; mi < 4; mi++)
                ldsm_x4(afr[mi], a_base + (mi * 16 * A_PITCH_H + kb) * 2);
            #pragma unroll
            for (int pr = 0; pr < 4; pr++) {
                uint32_t tmp[4];
                ldsm_x4(tmp, b_base + (pr * 16 * B_PITCH_H + kb) * 2);
                bfr[2 * pr][0]     = tmp[0];
                bfr[2 * pr + 1][0] = tmp[1];
                bfr[2 * pr][1]     = tmp[2];
                bfr[2 * pr + 1][1] = tmp[3];
            }
            #pragma unroll
            for (int mi = 0; mi < 4; mi++)
                #pragma unroll
                for (int ni = 0; ni < 8; ni++)
                    mma_f16(acc[mi][ni], afr[mi], bfr[ni]);
        }

        if ((c & 7) == 7) {
            const int n0 = nbase + (c >> 3) * 256;
            #pragma unroll
            for (int ni = 0; ni < 8; ni++) {
                const int nloc = n0 + wn * 64 + ni * 8 + ctg * 2;
                const float2 q2 = *(const float2*)&g_qb[b * UNITS + nloc];
                const float2 v2 = *(const float2*)&V[nloc];
                #pragma unroll
                for (int mi = 0; mi < 4; mi++) {
                    p[mi][0] = fmaf(tanh_fast(acc[mi][ni][0] + q2.x), v2.x, p[mi][0]);
                    p[mi][0] = fmaf(tanh_fast(acc[mi][ni][1] + q2.y), v2.y, p[mi][0]);
                    p[mi][1] = fmaf(tanh_fast(acc[mi][ni][2] + q2.x), v2.x, p[mi][1]);
                    p[mi][1] = fmaf(tanh_fast(acc[mi][ni][3] + q2.y), v2.y, p[mi][1]);
                }
            }
        }
    }

    #pragma unroll
    for (int mi = 0; mi < 4; mi++) {
        #pragma unroll
        for (int r = 0; r < 2; r++) {
            float v = p[mi][r];
            v += __shfl_xor_sync(0xffffffffu, v, 1);
            v += __shfl_xor_sync(0xffffffffu, v, 2);
            if (ctg == 0)
                atomicAdd(&s_sc[wm * 64 + mi * 16 + r * 8 + grp], v);
        }
    }
    __syncthreads();
    if (tid < 128) g_scores_part[nhalf][m0 + tid] = s_sc[tid];
}

// ---------------------------------------------------------------------------
// Kernel 3: fused softmax + context partial.
// Each (b, sp) block recomputes the softmax stats (cheap: 2x2048 loads +
// 2048 expf), caches e[] in smem, writes its w_out slice, then accumulates
// its S-split of the weighted sum. All blocks of a batch compute identical
// bm/inv (same data, same order) -> deterministic, single writer per output.
// ---------------------------------------------------------------------------
#define SPAN (SEQ / NSPLIT)   // 64

__global__ __launch_bounds__(256) void ctx_fused_kernel(float* __restrict__ w_out)
{
    __shared__ float e_sm[SEQ];      // 8KB
    __shared__ float sred[8];
    const int b   = blockIdx.x;
    const int sp  = blockIdx.y;
    const int tid = threadIdx.x;
    const float* sc0 = g_scores_part[0] + b * SEQ;
    const float* sc1 = g_scores_part[1] + b * SEQ;

    // ---- softmax stats ----
    float m = -1e30f;
    for (int i = tid; i < SEQ; i += 256) m = fmaxf(m, sc0[i] + sc1[i]);
    #pragma unroll
    for (int off = 16; off > 0; off >>= 1)
        m = fmaxf(m, __shfl_xor_sync(0xffffffffu, m, off));
    if ((tid & 31) == 0) sred[tid >> 5] = m;
    __syncthreads();
    if (tid == 0) {
        float mm = sred[0];
        #pragma unroll
        for (int i = 1; i < 8; i++) mm = fmaxf(mm, sred[i]);
        sred[0] = mm;
    }
    __syncthreads();
    const float bm = sred[0];
    __syncthreads();

    float sum = 0.f;
    for (int i = tid; i < SEQ; i += 256) {
        float e = __expf(sc0[i] + sc1[i] - bm);
        e_sm[i] = e;
        sum += e;
    }
    #pragma unroll
    for (int off = 16; off > 0; off >>= 1)
        sum += __shfl_xor_sync(0xffffffffu, sum, off);
    if ((tid & 31) == 0) sred[tid >> 5] = sum;
    __syncthreads();
    if (tid == 0) {
        float s = 0.f;
        #pragma unroll
        for (int i = 0; i < 8; i++) s += sred[i];
        sred[0] = s;
    }
    __syncthreads();
    const float inv = 1.f / sred[0];

    const int s0 = sp * SPAN;

    // ---- this split's slice of attention_weights output ----
    if (w_out) {
        for (int i = s0 + tid; i < s0 + SPAN; i += 256)
            w_out[b * SEQ + i] = e_sm[i] * inv;
    }

    // ---- weighted sum over this split's S range (4-way MLP) ----
    const uint2* vp = (const uint2*)(g_values_h + (size_t)b * SEQ * DIM);
    float4 acc = make_float4(0.f, 0.f, 0.f, 0.f);
    #pragma unroll 1
    for (int s = s0; s < s0 + SPAN; s += 4) {
        float w0 = e_sm[s]     * inv;
        float w1 = e_sm[s + 1] * inv;
        float w2 = e_sm[s + 2] * inv;
        float w3 = e_sm[s + 3] * inv;
        uint2 u0 = vp[(size_t)(s)     * 256 + tid];
        uint2 u1 = vp[(size_t)(s + 1) * 256 + tid];
        uint2 u2 = vp[(size_t)(s + 2) * 256 + tid];
        uint2 u3 = vp[(size_t)(s + 3) * 256 + tid];
        float2 a0 = __half22float2(*(const __half2*)&u0.x);
        float2 a1 = __half22float2(*(const __half2*)&u0.y);
        float2 b0 = __half22float2(*(const __half2*)&u1.x);
        float2 b1 = __half22float2(*(const __half2*)&u1.y);
        float2 c0 = __half22float2(*(const __half2*)&u2.x);
        float2 c1 = __half22float2(*(const __half2*)&u2.y);
        float2 d0 = __half22float2(*(const __half2*)&u3.x);
        float2 d1 = __half22float2(*(const __half2*)&u3.y);
        acc.x = fmaf(w0, a0.x, fmaf(w1, b0.x, fmaf(w2, c0.x, fmaf(w3, d0.x, acc.x))));
        acc.y = fmaf(w0, a0.y, fmaf(w1, b0.y, fmaf(w2, c0.y, fmaf(w3, d0.y, acc.y))));
        acc.z = fmaf(w0, a1.x, fmaf(w1, b1.x, fmaf(w2, c1.x, fmaf(w3, d1.x, acc.z))));
        acc.w = fmaf(w0, a1.y, fmaf(w1, b1.y, fmaf(w2, c1.y, fmaf(w3, d1.y, acc.w))));
    }
    ((float4*)&g_ctx_part[sp][b * DIM])[tid] = acc;
}

__global__ __launch_bounds__(256) void ctx_reduce_kernel(float* __restrict__ ctx_out)
{
    const int i = blockIdx.x * 256 + threadIdx.x;
    float acc = 0.f;
    #pragma unroll
    for (int p = 0; p < NSPLIT; p++) acc += g_ctx_part[p][i];
    ctx_out[i] = acc;
}

// ---------------------------------------------------------------------------
// Launch: inputs = query, values, W1, b1, W2, b2, V, bV
// ---------------------------------------------------------------------------
extern "C" void kernel_launch(void* const* d_in, const int* in_sizes, int n_in,
                              void* d_out, int out_size)
{
    const float* query  = (const float*)d_in[0];
    const float* values = (const float*)d_in[1];
    const float* W1     = (const float*)d_in[2];
    const float* b1     = (const float*)d_in[3];
    const float* W2     = (const float*)d_in[4];
    const float* b2     = (const float*)d_in[5];
    const float* V      = (const float*)d_in[6];
    // bV shifts every score equally -> softmax-invariant; unused.

    float* out = (float*)d_out;
    float* ctx_out = nullptr;
    float* w_out   = nullptr;
    if (out_size >= BATCH * DIM + BATCH * SEQ) {
        ctx_out = out;
        w_out   = out + BATCH * DIM;
    } else if (out_size == BATCH * SEQ) {
        w_out = out;
    } else {
        ctx_out = out;
    }

    static int smem_set = 0;
    if (!smem_set) {
        cudaFuncSetAttribute(score_kernel, cudaFuncAttributeMaxDynamicSharedMemorySize,
                             SMEM_SCORE_BYTES);
        smem_set = 1;
    }

    prep_kernel<<<PREP_GRID, 256>>>(query, values, W1, b1, W2, b2);
    score_kernel<<<(BATCH * SEQ) / 128 * 2, 256, SMEM_SCORE_BYTES>>>(V);
    ctx_fused_kernel<<<dim3(BATCH, NSPLIT), 256>>>(w_out);
    if (ctx_out)
        ctx_reduce_kernel<<<(BATCH * DIM) / 256, 256>>>(ctx_out);
}

// round 13
// speedup vs baseline: 1.1547x; 1.0223x over previous
#include <cuda_runtime.h>
#include <cuda_fp16.h>
#include <stdint.h>
#include <math.h>

#define BATCH 32
#define SEQ   2048
#define DIM   1024
#define UNITS 1024

// ---------------------------------------------------------------------------
// Scratch (no device allocs allowed)
// ---------------------------------------------------------------------------
#define NSPLIT  32      // S-splits for context
#define NPARTS  8       // N-splits for score
__device__ __half g_values_h[BATCH * SEQ * DIM];   // fp16 copy of values (128MB)
__device__ __half g_W1T_h[UNITS * DIM];            // W1 transposed, fp16 [u][d]
__device__ float  g_qb[BATCH * UNITS];             // query@W2 + b2 + b1
__device__ float  g_scores_part[NPARTS][BATCH * SEQ];
__device__ float  g_ctx_part[NSPLIT][BATCH * DIM];

// ---------------------------------------------------------------------------
// PTX helpers
// ---------------------------------------------------------------------------
__device__ __forceinline__ uint32_t smem_u32(const void* p) {
    uint32_t a;
    asm("{ .reg .u64 t; cvta.to.shared.u64 t, %1; cvt.u32.u64 %0, t; }" : "=r"(a) : "l"(p));
    return a;
}
#define CP_ASYNC16(s, g) \
    asm volatile("cp.async.cg.shared.global [%0], [%1], 16;" :: "r"(s), "l"(g))
#define CP_COMMIT() asm volatile("cp.async.commit_group;" ::: "memory")
#define CP_WAIT0()  asm volatile("cp.async.wait_group 0;" ::: "memory")

// mma.sync m16n8k16 fp16 inputs, fp32 accum (baseline PTX, sm_80+)
__device__ __forceinline__ void mma_f16(float* d, const uint32_t* a, const uint32_t* b) {
    asm volatile(
        "mma.sync.aligned.m16n8k16.row.col.f32.f16.f16.f32 "
        "{%0,%1,%2,%3}, {%4,%5,%6,%7}, {%8,%9}, {%0,%1,%2,%3};"
        : "+f"(d[0]), "+f"(d[1]), "+f"(d[2]), "+f"(d[3])
        : "r"(a[0]), "r"(a[1]), "r"(a[2]), "r"(a[3]), "r"(b[0]), "r"(b[1]));
}

// ldmatrix x4 (baseline PTX, sm_75+)
__device__ __forceinline__ void ldsm_x4(uint32_t* r, uint32_t saddr) {
    asm volatile("ldmatrix.sync.aligned.m8n8.x4.shared.b16 {%0,%1,%2,%3}, [%4];"
        : "=r"(r[0]), "=r"(r[1]), "=r"(r[2]), "=r"(r[3]) : "r"(saddr));
}

// ---------------------------------------------------------------------------
// FMA-only tanh (no MUFU): abs err < ~5e-5
// ---------------------------------------------------------------------------
__device__ __forceinline__ float tanh_fast(float x) {
    float ax = fminf(fabsf(x), 10.0f);
    float t  = ax * 2.885390081777927f;
    float fn = t + 12582912.0f;
    int   n  = __float_as_int(fn) - __float_as_int(12582912.0f);
    float f  = t - (fn - 12582912.0f);
    float p  = 9.6181e-3f;
    p = fmaf(p, f, 5.5504e-2f);
    p = fmaf(p, f, 2.4022651e-1f);
    p = fmaf(p, f, 6.9314718e-1f);
    p = fmaf(p, f, 1.0f);
    float e = __int_as_float(__float_as_int(p) + (n << 23));
    float d = e + 1.0f;
    float r = __int_as_float(0x7EF311C3u - __float_as_int(d));
    r = r * fmaf(-d, r, 2.0f);
    r = r * fmaf(-d, r, 2.0f);
    float th = fmaf(-2.0f, r, 1.0f);
    return __int_as_float(__float_as_int(th) | (__float_as_int(x) & 0x80000000));
}

// ---------------------------------------------------------------------------
// Fused prep kernel: heterogeneous blocks, all three jobs run concurrently.
// ---------------------------------------------------------------------------
#define PREP_QPROJ_BLKS  BATCH
#define PREP_TRANS_BLKS  ((DIM / 32) * (UNITS / 32))            // 1024
#define PREP_CONV_BLKS   ((BATCH * SEQ * DIM) / (256 * 8))      // 32768
#define PREP_GRID        (PREP_QPROJ_BLKS + PREP_TRANS_BLKS + PREP_CONV_BLKS)

__global__ __launch_bounds__(256) void prep_kernel(
    const float* __restrict__ query, const float* __restrict__ values,
    const float* __restrict__ W1,   const float* __restrict__ b1,
    const float* __restrict__ W2,   const float* __restrict__ b2)
{
    const int tid = threadIdx.x;
    const int bid = blockIdx.x;

    if (bid < PREP_QPROJ_BLKS) {
        __shared__ float qrow[DIM];
        const int b = bid;
        for (int i = tid; i < DIM; i += 256)
            qrow[i] = query[b * DIM + i];
        __syncthreads();
        for (int u = tid; u < UNITS; u += 256) {
            float acc = 0.f;
            #pragma unroll 8
            for (int d = 0; d < DIM; d++)
                acc = fmaf(qrow[d], W2[d * UNITS + u], acc);
            g_qb[b * UNITS + u] = acc + b1[u] + b2[u];
        }
    } else if (bid < PREP_QPROJ_BLKS + PREP_TRANS_BLKS) {
        __shared__ float t[32][33];
        const int tile = bid - PREP_QPROJ_BLKS;
        const int d0 = (tile & 31) * 32;
        const int u0 = (tile >> 5) * 32;
        const int tx = tid & 31;
        const int ty = tid >> 5;
        #pragma unroll
        for (int i = 0; i < 4; i++) {
            int r = ty + i * 8;
            t[r][tx] = W1[(size_t)(d0 + r) * UNITS + u0 + tx];
        }
        __syncthreads();
        #pragma unroll
        for (int i = 0; i < 4; i++) {
            int r = ty + i * 8;
            g_W1T_h[(size_t)(u0 + r) * DIM + d0 + tx] = __float2half_rn(t[tx][r]);
        }
    } else {
        const size_t idx = (size_t)(bid - PREP_QPROJ_BLKS - PREP_TRANS_BLKS) * 256 + tid;
        const float4* in = (const float4*)values;
        float4 v0 = in[idx * 2];
        float4 v1 = in[idx * 2 + 1];
        __half2 h0 = __floats2half2_rn(v0.x, v0.y);
        __half2 h1 = __floats2half2_rn(v0.z, v0.w);
        __half2 h2 = __floats2half2_rn(v1.x, v1.y);
        __half2 h3 = __floats2half2_rn(v1.z, v1.w);
        uint4 o;
        o.x = *(uint32_t*)&h0; o.y = *(uint32_t*)&h1;
        o.z = *(uint32_t*)&h2; o.w = *(uint32_t*)&h3;
        ((uint4*)g_values_h)[idx] = o;
    }
}

// ---------------------------------------------------------------------------
// Kernel 2: fused score GEMM via mma.sync fp16 (m16n8k16) + ldmatrix
// CTA tile 128(M) x 128(N) (one N-eighth), K chunks of 64 -> 16 chunks.
// Grid = 4096 (512 row tiles x 8 N-splits). 2 CTAs/SM (smem 74KB, regs<=128):
// co-resident CTAs desynchronize, overlapping one CTA's LDSM ramp with the
// other's MMA burst. 256 threads = 8 warps (2M x 4N), warp tile 64x32.
// 2-stage cp.async pipeline, epilogue once after the K loop.
// ---------------------------------------------------------------------------
#define KC        64
#define A_PITCH_H 72                   // 144 B rows: conflict-free LDSM + cp.async
#define B_PITCH_H 72
#define A_STAGE_H (128 * A_PITCH_H)    // 9216 halfs
#define B_STAGE_H (128 * B_PITCH_H)    // 9216 halfs
#define OFF_B_H   (2 * A_STAGE_H)      // 18432 halfs
#define SMEM_HALFS (OFF_B_H + 2 * B_STAGE_H)         // 36864 halfs
#define OFF_SC_BYTES (SMEM_HALFS * 2)                // 73728
#define SMEM_SCORE_BYTES (OFF_SC_BYTES + 128 * 4)    // 74240

__device__ __forceinline__ void load_chunk(uint32_t sb, int stage, int m0, int n0,
                                           int c, int tid)
{
    const int k0 = c * KC;
    const uint32_t a_s = sb + stage * A_STAGE_H * 2;
    const uint32_t b_s = sb + (OFF_B_H + stage * B_STAGE_H) * 2;
    // A: values_h tile 128 x 64 halfs (1024 16B chunks / 256 thr = 4)
    #pragma unroll
    for (int t = 0; t < 4; t++) {
        int idx = tid + t * 256;
        int r = idx >> 3, cc = idx & 7;
        CP_ASYNC16(a_s + r * 144 + cc * 16,
                   g_values_h + (size_t)(m0 + r) * DIM + k0 + cc * 8);
    }
    // B: W1T_h tile 128 x 64 halfs (1024 chunks / 256 thr = 4)
    #pragma unroll
    for (int t = 0; t < 4; t++) {
        int idx = tid + t * 256;
        int r = idx >> 3, cc = idx & 7;
        CP_ASYNC16(b_s + r * 144 + cc * 16,
                   g_W1T_h + (size_t)(n0 + r) * DIM + k0 + cc * 8);
    }
}

__global__ __launch_bounds__(256, 2) void score_kernel(const float* __restrict__ V)
{
    extern __shared__ __align__(16) char smraw[];
    float* s_sc = (float*)(smraw + OFF_SC_BYTES);
    const uint32_t sb = smem_u32(smraw);

    const int tid  = threadIdx.x;
    const int warp = tid >> 5;
    const int lane = tid & 31;
    const int wm   = warp >> 2;          // 0..1 (M)
    const int wn   = warp & 3;           // 0..3 (N)
    const int grp  = lane >> 2;          // 0..7
    const int ctg  = lane & 3;           // 0..3
    const int npart = blockIdx.x & 7;                // 0..7
    const int m0    = (blockIdx.x >> 3) * 128;
    const int nbase = npart * 128;
    const int b     = m0 >> 11;

    const int lrow = ((lane >> 3) & 1) * 8 + (lane & 7);   // 0..15
    const int lkoc = ((lane >> 4) & 1) * 8;                // 0 or 8

    if (tid < 128) s_sc[tid] = 0.f;

    float acc[4][4][4];
    #pragma unroll
    for (int mi = 0; mi < 4; mi++)
        #pragma unroll
        for (int ni = 0; ni < 4; ni++)
            #pragma unroll
            for (int r = 0; r < 4; r++)
                acc[mi][ni][r] = 0.f;

    load_chunk(sb, 0, m0, nbase, 0, tid); CP_COMMIT();

    for (int c = 0; c < 16; c++) {
        const int stage = c & 1;
        CP_WAIT0();
        __syncthreads();
        if (c + 1 < 16) {
            load_chunk(sb, (c + 1) & 1, m0, nbase, c + 1, tid);
            CP_COMMIT();
        }

        const uint32_t a_base = sb + stage * A_STAGE_H * 2
                              + ((wm * 64 + lrow) * A_PITCH_H + lkoc) * 2;
        const uint32_t b_base = sb + (OFF_B_H + stage * B_STAGE_H) * 2
                              + ((wn * 32 + lrow) * B_PITCH_H + lkoc) * 2;

        #pragma unroll
        for (int k16 = 0; k16 < KC / 16; k16++) {
            const int kb = k16 * 16;
            uint32_t afr[4][4], bfr[4][2];
            #pragma unroll
            for (int mi = 0; mi < 4; mi++)
                ldsm_x4(afr[mi], a_base + (mi * 16 * A_PITCH_H + kb) * 2);
            #pragma unroll
            for (int pr = 0; pr < 2; pr++) {
                uint32_t tmp[4];
                ldsm_x4(tmp, b_base + (pr * 16 * B_PITCH_H + kb) * 2);
                bfr[2 * pr][0]     = tmp[0];
                bfr[2 * pr + 1][0] = tmp[1];
                bfr[2 * pr][1]     = tmp[2];
                bfr[2 * pr + 1][1] = tmp[3];
            }
            #pragma unroll
            for (int mi = 0; mi < 4; mi++)
                #pragma unroll
                for (int ni = 0; ni < 4; ni++)
                    mma_f16(acc[mi][ni], afr[mi], bfr[ni]);
        }
        __syncthreads();
    }

    // epilogue: tanh(acc + qb) * V for this CTA's N-eighth
    float p[4][2];
    #pragma unroll
    for (int i = 0; i < 4; i++) { p[i][0] = 0.f; p[i][1] = 0.f; }
    #pragma unroll
    for (int ni = 0; ni < 4; ni++) {
        const int nloc = nbase + wn * 32 + ni * 8 + ctg * 2;
        const float2 q2 = *(const float2*)&g_qb[b * UNITS + nloc];
        const float2 v2 = *(const float2*)&V[nloc];
        #pragma unroll
        for (int mi = 0; mi < 4; mi++) {
            p[mi][0] = fmaf(tanh_fast(acc[mi][ni][0] + q2.x), v2.x, p[mi][0]);
            p[mi][0] = fmaf(tanh_fast(acc[mi][ni][1] + q2.y), v2.y, p[mi][0]);
            p[mi][1] = fmaf(tanh_fast(acc[mi][ni][2] + q2.x), v2.x, p[mi][1]);
            p[mi][1] = fmaf(tanh_fast(acc[mi][ni][3] + q2.y), v2.y, p[mi][1]);
        }
    }

    // reduce over quad lanes (ctg), then across the 4 n-warps via smem atomics
    #pragma unroll
    for (int mi = 0; mi < 4; mi++) {
        #pragma unroll
        for (int r = 0; r < 2; r++) {
            float v = p[mi][r];
            v += __shfl_xor_sync(0xffffffffu, v, 1);
            v += __shfl_xor_sync(0xffffffffu, v, 2);
            if (ctg == 0)
                atomicAdd(&s_sc[wm * 64 + mi * 16 + r * 8 + grp], v);
        }
    }
    __syncthreads();
    if (tid < 128) g_scores_part[npart][m0 + tid] = s_sc[tid];
}

// ---------------------------------------------------------------------------
// Kernel 3: fused softmax + context partial.
// Each (b, sp) block recomputes softmax stats from the 8 N-split partials
// (L2-hot), caches e[] in smem, writes its w_out slice, then accumulates
// its S-split of the weighted sum. Deterministic: identical stats everywhere,
// single writer per output element.
// ---------------------------------------------------------------------------
#define SPAN (SEQ / NSPLIT)   // 64

__global__ __launch_bounds__(256) void ctx_fused_kernel(float* __restrict__ w_out)
{
    __shared__ float e_sm[SEQ];      // 8KB
    __shared__ float sred[8];
    const int b   = blockIdx.x;
    const int sp  = blockIdx.y;
    const int tid = threadIdx.x;

    // ---- softmax stats (sum the 8 N-split partials) ----
    float m = -1e30f;
    for (int i = tid; i < SEQ; i += 256) {
        float s = 0.f;
        #pragma unroll
        for (int q = 0; q < NPARTS; q++) s += g_scores_part[q][b * SEQ + i];
        e_sm[i] = s;                      // stash raw score
        m = fmaxf(m, s);
    }
    #pragma unroll
    for (int off = 16; off > 0; off >>= 1)
        m = fmaxf(m, __shfl_xor_sync(0xffffffffu, m, off));
    if ((tid & 31) == 0) sred[tid >> 5] = m;
    __syncthreads();
    if (tid == 0) {
        float mm = sred[0];
        #pragma unroll
        for (int i = 1; i < 8; i++) mm = fmaxf(mm, sred[i]);
        sred[0] = mm;
    }
    __syncthreads();
    const float bm = sred[0];
    __syncthreads();

    float sum = 0.f;
    for (int i = tid; i < SEQ; i += 256) {
        float e = __expf(e_sm[i] - bm);
        e_sm[i] = e;
        sum += e;
    }
    __syncthreads();    // e_sm writes visible
    #pragma unroll
    for (int off = 16; off > 0; off >>= 1)
        sum += __shfl_xor_sync(0xffffffffu, sum, off);
    if ((tid & 31) == 0) sred[tid >> 5] = sum;
    __syncthreads();
    if (tid == 0) {
        float s = 0.f;
        #pragma unroll
        for (int i = 0; i < 8; i++) s += sred[i];
        sred[0] = s;
    }
    __syncthreads();
    const float inv = 1.f / sred[0];

    const int s0 = sp * SPAN;

    // ---- this split's slice of attention_weights output ----
    if (w_out) {
        for (int i = s0 + tid; i < s0 + SPAN; i += 256)
            w_out[b * SEQ + i] = e_sm[i] * inv;
    }

    // ---- weighted sum over this split's S range (4-way MLP) ----
    const uint2* vp = (const uint2*)(g_values_h + (size_t)b * SEQ * DIM);
    float4 acc = make_float4(0.f, 0.f, 0.f, 0.f);
    #pragma unroll 1
    for (int s = s0; s < s0 + SPAN; s += 4) {
        float w0 = e_sm[s]     * inv;
        float w1 = e_sm[s + 1] * inv;
        float w2 = e_sm[s + 2] * inv;
        float w3 = e_sm[s + 3] * inv;
        uint2 u0 = vp[(size_t)(s)     * 256 + tid];
        uint2 u1 = vp[(size_t)(s + 1) * 256 + tid];
        uint2 u2 = vp[(size_t)(s + 2) * 256 + tid];
        uint2 u3 = vp[(size_t)(s + 3) * 256 + tid];
        float2 a0 = __half22float2(*(const __half2*)&u0.x);
        float2 a1 = __half22float2(*(const __half2*)&u0.y);
        float2 b0 = __half22float2(*(const __half2*)&u1.x);
        float2 b1 = __half22float2(*(const __half2*)&u1.y);
        float2 c0 = __half22float2(*(const __half2*)&u2.x);
        float2 c1 = __half22float2(*(const __half2*)&u2.y);
        float2 d0 = __half22float2(*(const __half2*)&u3.x);
        float2 d1 = __half22float2(*(const __half2*)&u3.y);
        acc.x = fmaf(w0, a0.x, fmaf(w1, b0.x, fmaf(w2, c0.x, fmaf(w3, d0.x, acc.x))));
        acc.y = fmaf(w0, a0.y, fmaf(w1, b0.y, fmaf(w2, c0.y, fmaf(w3, d0.y, acc.y))));
        acc.z = fmaf(w0, a1.x, fmaf(w1, b1.x, fmaf(w2, c1.x, fmaf(w3, d1.x, acc.z))));
        acc.w = fmaf(w0, a1.y, fmaf(w1, b1.y, fmaf(w2, c1.y, fmaf(w3, d1.y, acc.w))));
    }
    ((float4*)&g_ctx_part[sp][b * DIM])[tid] = acc;
}

__global__ __launch_bounds__(256) void ctx_reduce_kernel(float* __restrict__ ctx_out)
{
    const int i = blockIdx.x * 256 + threadIdx.x;
    float acc = 0.f;
    #pragma unroll
    for (int p = 0; p < NSPLIT; p++) acc += g_ctx_part[p][i];
    ctx_out[i] = acc;
}

// ---------------------------------------------------------------------------
// Launch: inputs = query, values, W1, b1, W2, b2, V, bV
// ---------------------------------------------------------------------------
extern "C" void kernel_launch(void* const* d_in, const int* in_sizes, int n_in,
                              void* d_out, int out_size)
{
    const float* query  = (const float*)d_in[0];
    const float* values = (const float*)d_in[1];
    const float* W1     = (const float*)d_in[2];
    const float* b1     = (const float*)d_in[3];
    const float* W2     = (const float*)d_in[4];
    const float* b2     = (const float*)d_in[5];
    const float* V      = (const float*)d_in[6];
    // bV shifts every score equally -> softmax-invariant; unused.

    float* out = (float*)d_out;
    float* ctx_out = nullptr;
    float* w_out   = nullptr;
    if (out_size >= BATCH * DIM + BATCH * SEQ) {
        ctx_out = out;
        w_out   = out + BATCH * DIM;
    } else if (out_size == BATCH * SEQ) {
        w_out = out;
    } else {
        ctx_out = out;
    }

    static int smem_set = 0;
    if (!smem_set) {
        cudaFuncSetAttribute(score_kernel, cudaFuncAttributeMaxDynamicSharedMemorySize,
                             SMEM_SCORE_BYTES);
        smem_set = 1;
    }

    prep_kernel<<<PREP_GRID, 256>>>(query, values, W1, b1, W2, b2);
    score_kernel<<<(BATCH * SEQ) / 128 * NPARTS, 256, SMEM_SCORE_BYTES>>>(V);
    ctx_fused_kernel<<<dim3(BATCH, NSPLIT), 256>>>(w_out);
    if (ctx_out)
        ctx_reduce_kernel<<<(BATCH * DIM) / 256, 256>>>(ctx_out);
}